// round 11
// baseline (speedup 1.0000x reference)
#include <cuda_runtime.h>
#include <cuda_fp16.h>
#include <math.h>
#include <stdint.h>

// ---------------- problem constants ----------------
#define DDIM 1024
#define HDIM 4096
#define NEXP 8
#define NTOK 4096
#define CAPE 4096

// ---------------- tiling (dyn path: KSTAGE=64, 3 stages, 8 warps) ----------------
#define KS64 64
#define A_LD64 72                         // 64 halves + 8 skew
#define B_LD64 136                        // 128 halves + 8 skew
#define A_BYTES64 (128 * A_LD64 * 2)      // 18432
#define B_BYTES64 (KS64 * B_LD64 * 2)     // 17408
#define STAGE64 (A_BYTES64 + B_BYTES64)   // 35840
#define SMEM_DYN (3 * STAGE64)            // 107520

// ---------------- tiling (static fallback: KSTAGE=32, 2 stages, 8 warps) ----------------
#define KS32 32
#define A_LD32 40
#define B_LD32 136
#define A_BYTES32 (128 * A_LD32 * 2)      // 10240
#define B_BYTES32 (KS32 * B_LD32 * 2)     // 8704
#define STAGE32 (A_BYTES32 + B_BYTES32)   // 18944
#define SMEM_STA (2 * STAGE32)            // 37888

// ---------------- device scratch ----------------
__device__ int    g_counts[NEXP];
__device__ int    g_tokens[NEXP * CAPE];
__device__ float  g_wts[NEXP * CAPE];
__device__ float  g_probsum[NEXP];
__device__ __half g_x16[(size_t)NTOK * DDIM];
__device__ __half g_w1[(size_t)NEXP * DDIM * HDIM];
__device__ __half g_w2[(size_t)NEXP * HDIM * DDIM];
__device__ __half g_h16[(size_t)NEXP * CAPE * HDIM];

// ---------------- helpers ----------------
__device__ __forceinline__ uint32_t smem_u32(const void* p) {
    uint32_t a;
    asm("{ .reg .u64 t; cvta.to.shared.u64 t, %1; cvt.u32.u64 %0, t; }" : "=r"(a) : "l"(p));
    return a;
}
__device__ __forceinline__ void cp16(uint32_t s, const void* g) {
    asm volatile("cp.async.cg.shared.global [%0], [%1], 16;\n" :: "r"(s), "l"(g) : "memory");
}
__device__ __forceinline__ void cp_commit() {
    asm volatile("cp.async.commit_group;\n" ::: "memory");
}
template <int N>
__device__ __forceinline__ void cp_waitn() {
    asm volatile("cp.async.wait_group %0;\n" :: "n"(N) : "memory");
}
__device__ __forceinline__ void ldsm4(uint32_t& r0, uint32_t& r1, uint32_t& r2, uint32_t& r3, uint32_t a) {
    asm volatile("ldmatrix.sync.aligned.m8n8.x4.shared.b16 {%0,%1,%2,%3}, [%4];"
                 : "=r"(r0), "=r"(r1), "=r"(r2), "=r"(r3) : "r"(a));
}
__device__ __forceinline__ void ldsm4t(uint32_t& r0, uint32_t& r1, uint32_t& r2, uint32_t& r3, uint32_t a) {
    asm volatile("ldmatrix.sync.aligned.m8n8.x4.trans.shared.b16 {%0,%1,%2,%3}, [%4];"
                 : "=r"(r0), "=r"(r1), "=r"(r2), "=r"(r3) : "r"(a));
}
__device__ __forceinline__ void mma16816(float* c, const uint32_t* a, const uint32_t* b) {
    asm volatile(
        "mma.sync.aligned.m16n8k16.row.col.f32.f16.f16.f32 "
        "{%0,%1,%2,%3}, {%4,%5,%6,%7}, {%8,%9}, {%0,%1,%2,%3};"
        : "+f"(c[0]), "+f"(c[1]), "+f"(c[2]), "+f"(c[3])
        : "r"(a[0]), "r"(a[1]), "r"(a[2]), "r"(a[3]), "r"(b[0]), "r"(b[1]));
}

// ---------------- converts (16 elems/thread, 4 independent loads) ----------------
__device__ __forceinline__ void cvt16(const float* __restrict__ s,
                                      __half* __restrict__ d, size_t n) {
    size_t stride = (size_t)gridDim.x * blockDim.x * 16;
    for (size_t i = ((size_t)blockIdx.x * blockDim.x + threadIdx.x) * 16; i < n; i += stride) {
        float4 v0 = *(const float4*)(s + i);
        float4 v1 = *(const float4*)(s + i + 4);
        float4 v2 = *(const float4*)(s + i + 8);
        float4 v3 = *(const float4*)(s + i + 12);
        uint4 s0, s1;
        __half2 h;
        h = __halves2half2(__float2half_rn(v0.x), __float2half_rn(v0.y)); s0.x = *(uint32_t*)&h;
        h = __halves2half2(__float2half_rn(v0.z), __float2half_rn(v0.w)); s0.y = *(uint32_t*)&h;
        h = __halves2half2(__float2half_rn(v1.x), __float2half_rn(v1.y)); s0.z = *(uint32_t*)&h;
        h = __halves2half2(__float2half_rn(v1.z), __float2half_rn(v1.w)); s0.w = *(uint32_t*)&h;
        h = __halves2half2(__float2half_rn(v2.x), __float2half_rn(v2.y)); s1.x = *(uint32_t*)&h;
        h = __halves2half2(__float2half_rn(v2.z), __float2half_rn(v2.w)); s1.y = *(uint32_t*)&h;
        h = __halves2half2(__float2half_rn(v3.x), __float2half_rn(v3.y)); s1.z = *(uint32_t*)&h;
        h = __halves2half2(__float2half_rn(v3.z), __float2half_rn(v3.w)); s1.w = *(uint32_t*)&h;
        *(uint4*)(d + i)     = s0;
        *(uint4*)(d + i + 8) = s1;
    }
}
__global__ void k_cvt_x(const float* __restrict__ s) {
    if (blockIdx.x == 0 && threadIdx.x < NEXP) {
        g_counts[threadIdx.x] = 0;
        g_probsum[threadIdx.x] = 0.0f;
    }
    cvt16(s, g_x16, (size_t)NTOK * DDIM);
}
__global__ void k_cvt_w1(const float* __restrict__ s) {
    cvt16(s, g_w1, (size_t)NEXP * DDIM * HDIM);
}
__global__ void k_cvt_w2(const float* __restrict__ s) {
    cvt16(s, g_w2, (size_t)NEXP * HDIM * DDIM);
}

__global__ void k_router(const float* __restrict__ x, const float* __restrict__ rw) {
    int gwarp = (blockIdx.x * blockDim.x + threadIdx.x) >> 5;
    int lane  = threadIdx.x & 31;
    __shared__ float s_ps[NEXP];
    if (threadIdx.x < NEXP) s_ps[threadIdx.x] = 0.0f;
    __syncthreads();

    if (gwarp < NTOK) {
        const float* xr = x + (size_t)gwarp * DDIM;
        float acc[NEXP];
        #pragma unroll
        for (int e = 0; e < NEXP; e++) acc[e] = 0.0f;
        for (int k = lane; k < DDIM; k += 32) {
            float xv = xr[k];
            const float* r = rw + k * NEXP;
            #pragma unroll
            for (int e = 0; e < NEXP; e++) acc[e] += xv * r[e];
        }
        #pragma unroll
        for (int off = 16; off > 0; off >>= 1)
            #pragma unroll
            for (int e = 0; e < NEXP; e++)
                acc[e] += __shfl_down_sync(0xffffffffu, acc[e], off);

        if (lane == 0) {
            float m = acc[0];
            #pragma unroll
            for (int e = 1; e < NEXP; e++) m = fmaxf(m, acc[e]);
            float p[NEXP]; float Z = 0.0f;
            #pragma unroll
            for (int e = 0; e < NEXP; e++) { p[e] = expf(acc[e] - m); Z += p[e]; }
            float invZ = 1.0f / Z;
            #pragma unroll
            for (int e = 0; e < NEXP; e++) p[e] *= invZ;

            int i1 = 0;
            #pragma unroll
            for (int e = 1; e < NEXP; e++) if (p[e] > p[i1]) i1 = e;
            int i2 = (i1 == 0) ? 1 : 0;
            #pragma unroll
            for (int e = 0; e < NEXP; e++) if (e != i1 && p[e] > p[i2]) i2 = e;

            float s  = p[i1] + p[i2] + 1e-8f;
            int pos1 = atomicAdd(&g_counts[i1], 1);
            g_tokens[i1 * CAPE + pos1] = gwarp;
            g_wts[i1 * CAPE + pos1]    = p[i1] / s;
            int pos2 = atomicAdd(&g_counts[i2], 1);
            g_tokens[i2 * CAPE + pos2] = gwarp;
            g_wts[i2 * CAPE + pos2]    = p[i2] / s;

            #pragma unroll
            for (int e = 0; e < NEXP; e++) atomicAdd(&s_ps[e], p[e]);
        }
    }
    __syncthreads();
    if (threadIdx.x < NEXP) atomicAdd(&g_probsum[threadIdx.x], s_ps[threadIdx.x]);
}

__global__ void k_aux(float* __restrict__ out, int out_size) {
    if (threadIdx.x == 0 && out_size > NTOK * DDIM) {
        float aux = 0.0f;
        for (int e = 0; e < NEXP; e++) {
            float avg_p = g_probsum[e] / (float)NTOK;
            float usage = (float)g_counts[e] / (float)(NTOK * 2);
            aux += avg_p * usage;
        }
        out[NTOK * DDIM] = (float)NEXP * aux;
    }
}

__global__ void k_zero_out(float* __restrict__ out) {
    size_t n = (size_t)NTOK * DDIM;
    size_t stride = (size_t)gridDim.x * blockDim.x * 4;
    for (size_t i = ((size_t)blockIdx.x * blockDim.x + threadIdx.x) * 4; i < n; i += stride)
        *(float4*)(out + i) = make_float4(0.f, 0.f, 0.f, 0.f);
}

// ---------------- mainloop64: 8 warps, 64x32 warp tile, KS=64, 3 stages ----------------
template <int KTOT, int NS>
__device__ __forceinline__ void mainloop64(
    const __half* __restrict__ Abase,
    const __half* __restrict__ Bn0,
    const int* __restrict__ gather,
    int m0, int ne, char* dsm,
    float (&acc)[4][4][4], int wm, int wn)
{
    constexpr int STAGES = 3;
    const int tid = threadIdx.x;
    const int lane = tid & 31;
    uint32_t sbase = smem_u32(dsm);

    size_t aoff[4]; uint32_t adst[4];
    #pragma unroll
    for (int t = 0; t < 4; t++) {
        int c = tid + t * 256;
        int row = c >> 3, sub = c & 7;
        int m = m0 + row;
        int ridx = gather ? ((m < ne) ? gather[m] : 0) : m;
        aoff[t] = (size_t)ridx * KTOT + sub * 8;
        adst[t] = (uint32_t)(row * (A_LD64 * 2) + sub * 16);
    }
    size_t boff[4]; uint32_t bdst[4];
    #pragma unroll
    for (int t = 0; t < 4; t++) {
        int c = tid + t * 256;
        int row = c >> 4, sub = c & 15;
        boff[t] = (size_t)row * NS + sub * 8;
        bdst[t] = (uint32_t)(A_BYTES64 + row * (B_LD64 * 2) + sub * 16);
    }

    auto issue = [&](int ks) {
        uint32_t sb = sbase + (ks % STAGES) * STAGE64;
        int k0 = ks * KS64;
        #pragma unroll
        for (int t = 0; t < 4; t++) cp16(sb + adst[t], Abase + aoff[t] + k0);
        const __half* bk = Bn0 + (size_t)k0 * NS;
        #pragma unroll
        for (int t = 0; t < 4; t++) cp16(sb + bdst[t], bk + boff[t]);
        cp_commit();
    };

    const uint32_t a_lane = (uint32_t)((lane & 15) * (A_LD64 * 2) + (lane >> 4) * 16);
    const uint32_t b_lane = (uint32_t)((lane & 15) * (B_LD64 * 2) + (lane >> 4) * 16);

    constexpr int NK = KTOT / KS64;
    issue(0); issue(1);

    for (int ks = 0; ks < NK; ks++) {
        if (ks == NK - 1) cp_waitn<0>();
        else              cp_waitn<1>();
        __syncthreads();
        if (ks + 2 < NK) issue(ks + 2);

        uint32_t As = sbase + (ks % STAGES) * STAGE64;
        uint32_t Bs = As + A_BYTES64;

        #pragma unroll
        for (int kk = 0; kk < 4; kk++) {
            uint32_t b[8];
            uint32_t bb = Bs + kk * 16 * (B_LD64 * 2) + wn * 64 + b_lane;
            ldsm4t(b[0], b[1], b[2], b[3], bb);
            ldsm4t(b[4], b[5], b[6], b[7], bb + 32);
            #pragma unroll
            for (int i = 0; i < 4; i++) {
                uint32_t a[4];
                ldsm4(a[0], a[1], a[2], a[3],
                      As + (uint32_t)((wm * 64 + i * 16) * (A_LD64 * 2)) + kk * 32 + a_lane);
                #pragma unroll
                for (int jn = 0; jn < 4; jn++)
                    mma16816(acc[i][jn], a, &b[jn * 2]);
            }
        }
    }
}

// ---------------- mainloop32 (static fallback, 2-stage) ----------------
template <int KTOT, int NS>
__device__ __forceinline__ void mainloop32(
    const __half* __restrict__ Abase,
    const __half* __restrict__ Bn0,
    const int* __restrict__ gather,
    int m0, int ne, char* dsm,
    float (&acc)[4][4][4], int wm, int wn)
{
    const int tid = threadIdx.x;
    const int lane = tid & 31;
    uint32_t sbase = smem_u32(dsm);

    size_t aoff[2]; uint32_t adst[2];
    #pragma unroll
    for (int t = 0; t < 2; t++) {
        int c = tid + t * 256;
        int row = c >> 2, sub = c & 3;
        int m = m0 + row;
        int ridx = gather ? ((m < ne) ? gather[m] : 0) : m;
        aoff[t] = (size_t)ridx * KTOT + sub * 8;
        adst[t] = (uint32_t)(row * (A_LD32 * 2) + sub * 16);
    }
    size_t boff[2]; uint32_t bdst[2];
    #pragma unroll
    for (int t = 0; t < 2; t++) {
        int c = tid + t * 256;
        int row = c >> 4, sub = c & 15;
        boff[t] = (size_t)row * NS + sub * 8;
        bdst[t] = (uint32_t)(A_BYTES32 + row * (B_LD32 * 2) + sub * 16);
    }

    auto issue = [&](int ks) {
        uint32_t sb = sbase + (ks & 1) * STAGE32;
        int k0 = ks * KS32;
        cp16(sb + adst[0], Abase + aoff[0] + k0);
        cp16(sb + adst[1], Abase + aoff[1] + k0);
        const __half* bk = Bn0 + (size_t)k0 * NS;
        cp16(sb + bdst[0], bk + boff[0]);
        cp16(sb + bdst[1], bk + boff[1]);
        cp_commit();
    };

    const uint32_t a_lane = (uint32_t)((lane & 15) * (A_LD32 * 2) + (lane >> 4) * 16);
    const uint32_t b_lane = (uint32_t)((lane & 15) * (B_LD32 * 2) + (lane >> 4) * 16);

    constexpr int NK = KTOT / KS32;
    issue(0);

    for (int ks = 0; ks < NK; ks++) {
        cp_waitn<0>();
        __syncthreads();
        if (ks + 1 < NK) issue(ks + 1);

        uint32_t As = sbase + (ks & 1) * STAGE32;
        uint32_t Bs = As + A_BYTES32;

        #pragma unroll
        for (int kk = 0; kk < 2; kk++) {
            uint32_t b[8];
            uint32_t bb = Bs + kk * 16 * (B_LD32 * 2) + wn * 64 + b_lane;
            ldsm4t(b[0], b[1], b[2], b[3], bb);
            ldsm4t(b[4], b[5], b[6], b[7], bb + 32);
            #pragma unroll
            for (int i = 0; i < 4; i++) {
                uint32_t a[4];
                ldsm4(a[0], a[1], a[2], a[3],
                      As + (uint32_t)((wm * 64 + i * 16) * (A_LD32 * 2)) + kk * 32 + a_lane);
                #pragma unroll
                for (int jn = 0; jn < 4; jn++)
                    mma16816(acc[i][jn], a, &b[jn * 2]);
            }
        }
    }
}

// ---------------- epilogues ----------------
__device__ __forceinline__ void epi1(int e, int ne, int m0, int n0, int wm, int wn,
                                     int lane, float (&acc)[4][4][4],
                                     const float* __restrict__ bin) {
    int gid = lane >> 2, t4 = lane & 3;
    #pragma unroll
    for (int i = 0; i < 4; i++) {
        int r0 = m0 + wm * 64 + i * 16 + gid;
        int r1 = r0 + 8;
        #pragma unroll
        for (int jn = 0; jn < 4; jn++) {
            int col = n0 + wn * 32 + jn * 8 + t4 * 2;
            float b0 = bin[e * HDIM + col], b1 = bin[e * HDIM + col + 1];
            if (r0 < ne) {
                float v0 = acc[i][jn][0] + b0;
                float v1 = acc[i][jn][1] + b1;
                v0 = 0.5f * v0 * (1.0f + erff(v0 * 0.70710678118654752f));
                v1 = 0.5f * v1 * (1.0f + erff(v1 * 0.70710678118654752f));
                *(__half2*)(g_h16 + ((size_t)e * CAPE + r0) * HDIM + col) =
                    __halves2half2(__float2half_rn(v0), __float2half_rn(v1));
            }
            if (r1 < ne) {
                float v2 = acc[i][jn][2] + b0;
                float v3 = acc[i][jn][3] + b1;
                v2 = 0.5f * v2 * (1.0f + erff(v2 * 0.70710678118654752f));
                v3 = 0.5f * v3 * (1.0f + erff(v3 * 0.70710678118654752f));
                *(__half2*)(g_h16 + ((size_t)e * CAPE + r1) * HDIM + col) =
                    __halves2half2(__float2half_rn(v2), __float2half_rn(v3));
            }
        }
    }
}

__device__ __forceinline__ void epi2(int e, int ne, int m0, int n0, int wm, int wn,
                                     int lane, float (&acc)[4][4][4],
                                     const float* __restrict__ bout,
                                     float* __restrict__ out) {
    int gid = lane >> 2, t4 = lane & 3;
    #pragma unroll
    for (int i = 0; i < 4; i++) {
        int r0 = m0 + wm * 64 + i * 16 + gid;
        int r1 = r0 + 8;
        int tok0 = -1, tok1 = -1; float wt0 = 0.0f, wt1 = 0.0f;
        if (r0 < ne) { tok0 = g_tokens[e * CAPE + r0]; wt0 = g_wts[e * CAPE + r0]; }
        if (r1 < ne) { tok1 = g_tokens[e * CAPE + r1]; wt1 = g_wts[e * CAPE + r1]; }
        #pragma unroll
        for (int jn = 0; jn < 4; jn++) {
            int col = n0 + wn * 32 + jn * 8 + t4 * 2;
            float b0 = bout[e * DDIM + col], b1 = bout[e * DDIM + col + 1];
            if (tok0 >= 0) {
                atomicAdd(out + (size_t)tok0 * DDIM + col,     wt0 * (acc[i][jn][0] + b0));
                atomicAdd(out + (size_t)tok0 * DDIM + col + 1, wt0 * (acc[i][jn][1] + b1));
            }
            if (tok1 >= 0) {
                atomicAdd(out + (size_t)tok1 * DDIM + col,     wt1 * (acc[i][jn][2] + b0));
                atomicAdd(out + (size_t)tok1 * DDIM + col + 1, wt1 * (acc[i][jn][3] + b1));
            }
        }
    }
}

// ---------------- gemm kernels ----------------
__global__ __launch_bounds__(256, 2) void k_gemm1_dyn(const float* __restrict__ bin) {
    extern __shared__ __align__(32) char dsm[];
    int e  = blockIdx.z;
    int ne = g_counts[e];
    int m0 = blockIdx.y * 128;
    if (m0 >= ne) return;
    int n0 = blockIdx.x * 128;
    int tid = threadIdx.x, wid = tid >> 5, lane = tid & 31;
    int wm = wid >> 2, wn = wid & 3;

    float acc[4][4][4];
    #pragma unroll
    for (int i = 0; i < 4; i++)
        #pragma unroll
        for (int j = 0; j < 4; j++)
            #pragma unroll
            for (int q = 0; q < 4; q++) acc[i][j][q] = 0.0f;

    mainloop64<DDIM, HDIM>(g_x16, g_w1 + (size_t)e * DDIM * HDIM + n0,
                           g_tokens + e * CAPE, m0, ne, dsm, acc, wm, wn);
    epi1(e, ne, m0, n0, wm, wn, lane, acc, bin);
}

__global__ __launch_bounds__(256, 2) void k_gemm2_dyn(const float* __restrict__ bout,
                                                      float* __restrict__ out) {
    extern __shared__ __align__(32) char dsm[];
    int e  = blockIdx.z;
    int ne = g_counts[e];
    int m0 = blockIdx.y * 128;
    if (m0 >= ne) return;
    int n0 = blockIdx.x * 128;
    int tid = threadIdx.x, wid = tid >> 5, lane = tid & 31;
    int wm = wid >> 2, wn = wid & 3;

    float acc[4][4][4];
    #pragma unroll
    for (int i = 0; i < 4; i++)
        #pragma unroll
        for (int j = 0; j < 4; j++)
            #pragma unroll
            for (int q = 0; q < 4; q++) acc[i][j][q] = 0.0f;

    mainloop64<HDIM, DDIM>(g_h16 + (size_t)e * CAPE * HDIM,
                           g_w2 + (size_t)e * HDIM * DDIM + n0,
                           nullptr, m0, ne, dsm, acc, wm, wn);
    epi2(e, ne, m0, n0, wm, wn, lane, acc, bout, out);
}

__global__ __launch_bounds__(256) void k_gemm1_sta(const float* __restrict__ bin) {
    __shared__ __align__(32) char dsm[SMEM_STA];
    int e  = blockIdx.z;
    int ne = g_counts[e];
    int m0 = blockIdx.y * 128;
    if (m0 >= ne) return;
    int n0 = blockIdx.x * 128;
    int tid = threadIdx.x, wid = tid >> 5, lane = tid & 31;
    int wm = wid >> 2, wn = wid & 3;

    float acc[4][4][4];
    #pragma unroll
    for (int i = 0; i < 4; i++)
        #pragma unroll
        for (int j = 0; j < 4; j++)
            #pragma unroll
            for (int q = 0; q < 4; q++) acc[i][j][q] = 0.0f;

    mainloop32<DDIM, HDIM>(g_x16, g_w1 + (size_t)e * DDIM * HDIM + n0,
                           g_tokens + e * CAPE, m0, ne, dsm, acc, wm, wn);
    epi1(e, ne, m0, n0, wm, wn, lane, acc, bin);
}

__global__ __launch_bounds__(256) void k_gemm2_sta(const float* __restrict__ bout,
                                                   float* __restrict__ out) {
    __shared__ __align__(32) char dsm[SMEM_STA];
    int e  = blockIdx.z;
    int ne = g_counts[e];
    int m0 = blockIdx.y * 128;
    if (m0 >= ne) return;
    int n0 = blockIdx.x * 128;
    int tid = threadIdx.x, wid = tid >> 5, lane = tid & 31;
    int wm = wid >> 2, wn = wid & 3;

    float acc[4][4][4];
    #pragma unroll
    for (int i = 0; i < 4; i++)
        #pragma unroll
        for (int j = 0; j < 4; j++)
            #pragma unroll
            for (int q = 0; q < 4; q++) acc[i][j][q] = 0.0f;

    mainloop32<HDIM, DDIM>(g_h16 + (size_t)e * CAPE * HDIM,
                           g_w2 + (size_t)e * HDIM * DDIM + n0,
                           nullptr, m0, ne, dsm, acc, wm, wn);
    epi2(e, ne, m0, n0, wm, wn, lane, acc, bout, out);
}

// ---------------- launch ----------------
extern "C" void kernel_launch(void* const* d_in, const int* in_sizes, int n_in,
                              void* d_out, int out_size) {
    const float* x    = (const float*)d_in[0];
    const float* rw   = (const float*)d_in[1];
    const float* Win  = (const float*)d_in[2];
    const float* bin  = (const float*)d_in[3];
    const float* Wout = (const float*)d_in[4];
    const float* bout = (const float*)d_in[5];
    float* out = (float*)d_out;

    cudaError_t a1 = cudaFuncSetAttribute(
        k_gemm1_dyn, cudaFuncAttributeMaxDynamicSharedMemorySize, SMEM_DYN);
    cudaError_t a2 = cudaFuncSetAttribute(
        k_gemm2_dyn, cudaFuncAttributeMaxDynamicSharedMemorySize, SMEM_DYN);
    bool use_dyn = (a1 == cudaSuccess) && (a2 == cudaSuccess);

    dim3 g1(HDIM / 128, CAPE / 128, NEXP);
    dim3 g2(DDIM / 128, CAPE / 128, NEXP);

    // ---- fork/join multi-stream schedule (graph-capturable) ----
    cudaStream_t s2 = nullptr;
    cudaEvent_t e0 = nullptr, e1 = nullptr, e2 = nullptr;
    bool par = (cudaStreamCreateWithFlags(&s2, cudaStreamNonBlocking) == cudaSuccess);
    if (par) par = (cudaEventCreateWithFlags(&e0, cudaEventDisableTiming) == cudaSuccess);
    if (par) par = (cudaEventCreateWithFlags(&e1, cudaEventDisableTiming) == cudaSuccess);
    if (par) par = (cudaEventCreateWithFlags(&e2, cudaEventDisableTiming) == cudaSuccess);

    if (par) {
        // fork: s2 branches off the capture-origin (legacy) stream
        cudaEventRecord(e0, 0);
        cudaStreamWaitEvent(s2, e0, 0);

        // weight path on s2: w1 convert (needed by gemm1), then w2 + zero (needed by gemm2)
        k_cvt_w1<<<4096, 256, 0, s2>>>(Win);
        cudaEventRecord(e1, s2);
        k_cvt_w2<<<4096, 256, 0, s2>>>(Wout);
        k_zero_out<<<512, 256, 0, s2>>>(out);
        cudaEventRecord(e2, s2);

        // x path on main stream, concurrent with cvt_w1
        k_cvt_x<<<1024, 256>>>(x);           // also zeroes routing state
        k_router<<<NTOK / 8, 256>>>(x, rw);

        // join w1 before gemm1; cvt_w2/zero continue under gemm1
        cudaStreamWaitEvent(0, e1, 0);
        if (use_dyn) k_gemm1_dyn<<<g1, 256, SMEM_DYN>>>(bin);
        else         k_gemm1_sta<<<g1, 256>>>(bin);

        // join w2 + zero before gemm2
        cudaStreamWaitEvent(0, e2, 0);
        if (use_dyn) k_gemm2_dyn<<<g2, 256, SMEM_DYN>>>(bout, out);
        else         k_gemm2_sta<<<g2, 256>>>(bout, out);
        k_aux<<<1, 32>>>(out, out_size);

        // s2's capture segment is joined; safe to release host handles
        cudaEventDestroy(e0);
        cudaEventDestroy(e1);
        cudaEventDestroy(e2);
        cudaStreamDestroy(s2);
    } else {
        if (e0) cudaEventDestroy(e0);
        if (e1) cudaEventDestroy(e1);
        if (e2) cudaEventDestroy(e2);
        if (s2) cudaStreamDestroy(s2);
        // serial fallback (R8-proven order)
        k_cvt_x<<<1024, 256>>>(x);
        k_router<<<NTOK / 8, 256>>>(x, rw);
        k_cvt_w1<<<4096, 256>>>(Win);
        if (use_dyn) k_gemm1_dyn<<<g1, 256, SMEM_DYN>>>(bin);
        else         k_gemm1_sta<<<g1, 256>>>(bin);
        k_cvt_w2<<<4096, 256>>>(Wout);
        k_zero_out<<<512, 256>>>(out);
        if (use_dyn) k_gemm2_dyn<<<g2, 256, SMEM_DYN>>>(bout, out);
        else         k_gemm2_sta<<<g2, 256>>>(bout, out);
        k_aux<<<1, 32>>>(out, out_size);
    }
}

// round 12
// speedup vs baseline: 1.0434x; 1.0434x over previous
#include <cuda_runtime.h>
#include <cuda_fp16.h>
#include <math.h>
#include <stdint.h>

// ---------------- problem constants ----------------
#define DDIM 1024
#define HDIM 4096
#define NEXP 8
#define NTOK 4096
#define CAPE 4096

// ---------------- tiling (dyn path: KSTAGE=64, 3 stages, 8 warps) ----------------
#define KS64 64
#define A_LD64 72                         // 64 halves + 8 skew
#define B_LD64 136                        // 128 halves + 8 skew
#define A_BYTES64 (128 * A_LD64 * 2)      // 18432
#define B_BYTES64 (KS64 * B_LD64 * 2)     // 17408
#define STAGE64 (A_BYTES64 + B_BYTES64)   // 35840
#define SMEM_DYN (3 * STAGE64)            // 107520

// ---------------- tiling (static fallback: KSTAGE=32, 2 stages, 8 warps) ----------------
#define KS32 32
#define A_LD32 40
#define B_LD32 136
#define A_BYTES32 (128 * A_LD32 * 2)      // 10240
#define B_BYTES32 (KS32 * B_LD32 * 2)     // 8704
#define STAGE32 (A_BYTES32 + B_BYTES32)   // 18944
#define SMEM_STA (2 * STAGE32)            // 37888

// ---------------- device scratch ----------------
__device__ int    g_counts[NEXP];
__device__ int    g_tokens[NEXP * CAPE];
__device__ float  g_wts[NEXP * CAPE];
__device__ float  g_probsum[NEXP];
__device__ __half g_x16[(size_t)NTOK * DDIM];
__device__ __half g_w1[(size_t)NEXP * DDIM * HDIM];
__device__ __half g_w2[(size_t)NEXP * HDIM * DDIM];
__device__ __half g_h16[(size_t)NEXP * CAPE * HDIM];

// ---------------- helpers ----------------
__device__ __forceinline__ uint32_t smem_u32(const void* p) {
    uint32_t a;
    asm("{ .reg .u64 t; cvta.to.shared.u64 t, %1; cvt.u32.u64 %0, t; }" : "=r"(a) : "l"(p));
    return a;
}
__device__ __forceinline__ void cp16(uint32_t s, const void* g) {
    asm volatile("cp.async.cg.shared.global [%0], [%1], 16;\n" :: "r"(s), "l"(g) : "memory");
}
__device__ __forceinline__ void cp_commit() {
    asm volatile("cp.async.commit_group;\n" ::: "memory");
}
template <int N>
__device__ __forceinline__ void cp_waitn() {
    asm volatile("cp.async.wait_group %0;\n" :: "n"(N) : "memory");
}
__device__ __forceinline__ void ldsm4(uint32_t& r0, uint32_t& r1, uint32_t& r2, uint32_t& r3, uint32_t a) {
    asm volatile("ldmatrix.sync.aligned.m8n8.x4.shared.b16 {%0,%1,%2,%3}, [%4];"
                 : "=r"(r0), "=r"(r1), "=r"(r2), "=r"(r3) : "r"(a));
}
__device__ __forceinline__ void ldsm4t(uint32_t& r0, uint32_t& r1, uint32_t& r2, uint32_t& r3, uint32_t a) {
    asm volatile("ldmatrix.sync.aligned.m8n8.x4.trans.shared.b16 {%0,%1,%2,%3}, [%4];"
                 : "=r"(r0), "=r"(r1), "=r"(r2), "=r"(r3) : "r"(a));
}
__device__ __forceinline__ void mma16816(float* c, const uint32_t* a, const uint32_t* b) {
    asm volatile(
        "mma.sync.aligned.m16n8k16.row.col.f32.f16.f16.f32 "
        "{%0,%1,%2,%3}, {%4,%5,%6,%7}, {%8,%9}, {%0,%1,%2,%3};"
        : "+f"(c[0]), "+f"(c[1]), "+f"(c[2]), "+f"(c[3])
        : "r"(a[0]), "r"(a[1]), "r"(a[2]), "r"(a[3]), "r"(b[0]), "r"(b[1]));
}

// ---------------- converts (16 elems/thread, evict-first fp32 reads) ----------------
__device__ __forceinline__ void cvt16(const float* __restrict__ s,
                                      __half* __restrict__ d, size_t n) {
    size_t stride = (size_t)gridDim.x * blockDim.x * 16;
    for (size_t i = ((size_t)blockIdx.x * blockDim.x + threadIdx.x) * 16; i < n; i += stride) {
        float4 v0 = __ldcs((const float4*)(s + i));
        float4 v1 = __ldcs((const float4*)(s + i + 4));
        float4 v2 = __ldcs((const float4*)(s + i + 8));
        float4 v3 = __ldcs((const float4*)(s + i + 12));
        uint4 s0, s1;
        __half2 h;
        h = __halves2half2(__float2half_rn(v0.x), __float2half_rn(v0.y)); s0.x = *(uint32_t*)&h;
        h = __halves2half2(__float2half_rn(v0.z), __float2half_rn(v0.w)); s0.y = *(uint32_t*)&h;
        h = __halves2half2(__float2half_rn(v1.x), __float2half_rn(v1.y)); s0.z = *(uint32_t*)&h;
        h = __halves2half2(__float2half_rn(v1.z), __float2half_rn(v1.w)); s0.w = *(uint32_t*)&h;
        h = __halves2half2(__float2half_rn(v2.x), __float2half_rn(v2.y)); s1.x = *(uint32_t*)&h;
        h = __halves2half2(__float2half_rn(v2.z), __float2half_rn(v2.w)); s1.y = *(uint32_t*)&h;
        h = __halves2half2(__float2half_rn(v3.x), __float2half_rn(v3.y)); s1.z = *(uint32_t*)&h;
        h = __halves2half2(__float2half_rn(v3.z), __float2half_rn(v3.w)); s1.w = *(uint32_t*)&h;
        *(uint4*)(d + i)     = s0;
        *(uint4*)(d + i + 8) = s1;
    }
}
__global__ void k_cvt_x(const float* __restrict__ s) {
    if (blockIdx.x == 0 && threadIdx.x < NEXP) {
        g_counts[threadIdx.x] = 0;
        g_probsum[threadIdx.x] = 0.0f;
    }
    cvt16(s, g_x16, (size_t)NTOK * DDIM);
}
__global__ void k_cvt_w1(const float* __restrict__ s) {
    cvt16(s, g_w1, (size_t)NEXP * DDIM * HDIM);
}
__global__ void k_cvt_w2(const float* __restrict__ s) {
    cvt16(s, g_w2, (size_t)NEXP * HDIM * DDIM);
}

__global__ void k_router(const float* __restrict__ x, const float* __restrict__ rw) {
    int gwarp = (blockIdx.x * blockDim.x + threadIdx.x) >> 5;
    int lane  = threadIdx.x & 31;
    __shared__ float s_ps[NEXP];
    if (threadIdx.x < NEXP) s_ps[threadIdx.x] = 0.0f;
    __syncthreads();

    if (gwarp < NTOK) {
        const float* xr = x + (size_t)gwarp * DDIM;
        float acc[NEXP];
        #pragma unroll
        for (int e = 0; e < NEXP; e++) acc[e] = 0.0f;
        for (int k = lane; k < DDIM; k += 32) {
            float xv = xr[k];
            const float* r = rw + k * NEXP;
            #pragma unroll
            for (int e = 0; e < NEXP; e++) acc[e] += xv * r[e];
        }
        #pragma unroll
        for (int off = 16; off > 0; off >>= 1)
            #pragma unroll
            for (int e = 0; e < NEXP; e++)
                acc[e] += __shfl_down_sync(0xffffffffu, acc[e], off);

        if (lane == 0) {
            float m = acc[0];
            #pragma unroll
            for (int e = 1; e < NEXP; e++) m = fmaxf(m, acc[e]);
            float p[NEXP]; float Z = 0.0f;
            #pragma unroll
            for (int e = 0; e < NEXP; e++) { p[e] = expf(acc[e] - m); Z += p[e]; }
            float invZ = 1.0f / Z;
            #pragma unroll
            for (int e = 0; e < NEXP; e++) p[e] *= invZ;

            int i1 = 0;
            #pragma unroll
            for (int e = 1; e < NEXP; e++) if (p[e] > p[i1]) i1 = e;
            int i2 = (i1 == 0) ? 1 : 0;
            #pragma unroll
            for (int e = 0; e < NEXP; e++) if (e != i1 && p[e] > p[i2]) i2 = e;

            float s  = p[i1] + p[i2] + 1e-8f;
            int pos1 = atomicAdd(&g_counts[i1], 1);
            g_tokens[i1 * CAPE + pos1] = gwarp;
            g_wts[i1 * CAPE + pos1]    = p[i1] / s;
            int pos2 = atomicAdd(&g_counts[i2], 1);
            g_tokens[i2 * CAPE + pos2] = gwarp;
            g_wts[i2 * CAPE + pos2]    = p[i2] / s;

            #pragma unroll
            for (int e = 0; e < NEXP; e++) atomicAdd(&s_ps[e], p[e]);
        }
    }
    __syncthreads();
    if (threadIdx.x < NEXP) atomicAdd(&g_probsum[threadIdx.x], s_ps[threadIdx.x]);
}

__global__ void k_aux(float* __restrict__ out, int out_size) {
    if (threadIdx.x == 0 && out_size > NTOK * DDIM) {
        float aux = 0.0f;
        for (int e = 0; e < NEXP; e++) {
            float avg_p = g_probsum[e] / (float)NTOK;
            float usage = (float)g_counts[e] / (float)(NTOK * 2);
            aux += avg_p * usage;
        }
        out[NTOK * DDIM] = (float)NEXP * aux;
    }
}

__global__ void k_zero_out(float* __restrict__ out) {
    size_t n = (size_t)NTOK * DDIM;
    size_t stride = (size_t)gridDim.x * blockDim.x * 4;
    for (size_t i = ((size_t)blockIdx.x * blockDim.x + threadIdx.x) * 4; i < n; i += stride)
        *(float4*)(out + i) = make_float4(0.f, 0.f, 0.f, 0.f);
}

// ---------------- mainloop64: 8 warps, 64x32 warp tile, KS=64, 3 stages ----------------
template <int KTOT, int NS>
__device__ __forceinline__ void mainloop64(
    const __half* __restrict__ Abase,
    const __half* __restrict__ Bn0,
    const int* __restrict__ gather,
    int m0, int ne, char* dsm,
    float (&acc)[4][4][4], int wm, int wn)
{
    constexpr int STAGES = 3;
    const int tid = threadIdx.x;
    const int lane = tid & 31;
    uint32_t sbase = smem_u32(dsm);

    size_t aoff[4]; uint32_t adst[4];
    #pragma unroll
    for (int t = 0; t < 4; t++) {
        int c = tid + t * 256;
        int row = c >> 3, sub = c & 7;
        int m = m0 + row;
        int ridx = gather ? ((m < ne) ? gather[m] : 0) : m;
        aoff[t] = (size_t)ridx * KTOT + sub * 8;
        adst[t] = (uint32_t)(row * (A_LD64 * 2) + sub * 16);
    }
    size_t boff[4]; uint32_t bdst[4];
    #pragma unroll
    for (int t = 0; t < 4; t++) {
        int c = tid + t * 256;
        int row = c >> 4, sub = c & 15;
        boff[t] = (size_t)row * NS + sub * 8;
        bdst[t] = (uint32_t)(A_BYTES64 + row * (B_LD64 * 2) + sub * 16);
    }

    auto issue = [&](int ks) {
        uint32_t sb = sbase + (ks % STAGES) * STAGE64;
        int k0 = ks * KS64;
        #pragma unroll
        for (int t = 0; t < 4; t++) cp16(sb + adst[t], Abase + aoff[t] + k0);
        const __half* bk = Bn0 + (size_t)k0 * NS;
        #pragma unroll
        for (int t = 0; t < 4; t++) cp16(sb + bdst[t], bk + boff[t]);
        cp_commit();
    };

    const uint32_t a_lane = (uint32_t)((lane & 15) * (A_LD64 * 2) + (lane >> 4) * 16);
    const uint32_t b_lane = (uint32_t)((lane & 15) * (B_LD64 * 2) + (lane >> 4) * 16);

    constexpr int NK = KTOT / KS64;
    issue(0); issue(1);

    for (int ks = 0; ks < NK; ks++) {
        if (ks == NK - 1) cp_waitn<0>();
        else              cp_waitn<1>();
        __syncthreads();
        if (ks + 2 < NK) issue(ks + 2);

        uint32_t As = sbase + (ks % STAGES) * STAGE64;
        uint32_t Bs = As + A_BYTES64;

        #pragma unroll
        for (int kk = 0; kk < 4; kk++) {
            uint32_t b[8];
            uint32_t bb = Bs + kk * 16 * (B_LD64 * 2) + wn * 64 + b_lane;
            ldsm4t(b[0], b[1], b[2], b[3], bb);
            ldsm4t(b[4], b[5], b[6], b[7], bb + 32);
            #pragma unroll
            for (int i = 0; i < 4; i++) {
                uint32_t a[4];
                ldsm4(a[0], a[1], a[2], a[3],
                      As + (uint32_t)((wm * 64 + i * 16) * (A_LD64 * 2)) + kk * 32 + a_lane);
                #pragma unroll
                for (int jn = 0; jn < 4; jn++)
                    mma16816(acc[i][jn], a, &b[jn * 2]);
            }
        }
    }
}

// ---------------- mainloop32 (static fallback, 2-stage) ----------------
template <int KTOT, int NS>
__device__ __forceinline__ void mainloop32(
    const __half* __restrict__ Abase,
    const __half* __restrict__ Bn0,
    const int* __restrict__ gather,
    int m0, int ne, char* dsm,
    float (&acc)[4][4][4], int wm, int wn)
{
    const int tid = threadIdx.x;
    const int lane = tid & 31;
    uint32_t sbase = smem_u32(dsm);

    size_t aoff[2]; uint32_t adst[2];
    #pragma unroll
    for (int t = 0; t < 2; t++) {
        int c = tid + t * 256;
        int row = c >> 2, sub = c & 3;
        int m = m0 + row;
        int ridx = gather ? ((m < ne) ? gather[m] : 0) : m;
        aoff[t] = (size_t)ridx * KTOT + sub * 8;
        adst[t] = (uint32_t)(row * (A_LD32 * 2) + sub * 16);
    }
    size_t boff[2]; uint32_t bdst[2];
    #pragma unroll
    for (int t = 0; t < 2; t++) {
        int c = tid + t * 256;
        int row = c >> 4, sub = c & 15;
        boff[t] = (size_t)row * NS + sub * 8;
        bdst[t] = (uint32_t)(A_BYTES32 + row * (B_LD32 * 2) + sub * 16);
    }

    auto issue = [&](int ks) {
        uint32_t sb = sbase + (ks & 1) * STAGE32;
        int k0 = ks * KS32;
        cp16(sb + adst[0], Abase + aoff[0] + k0);
        cp16(sb + adst[1], Abase + aoff[1] + k0);
        const __half* bk = Bn0 + (size_t)k0 * NS;
        cp16(sb + bdst[0], bk + boff[0]);
        cp16(sb + bdst[1], bk + boff[1]);
        cp_commit();
    };

    const uint32_t a_lane = (uint32_t)((lane & 15) * (A_LD32 * 2) + (lane >> 4) * 16);
    const uint32_t b_lane = (uint32_t)((lane & 15) * (B_LD32 * 2) + (lane >> 4) * 16);

    constexpr int NK = KTOT / KS32;
    issue(0);

    for (int ks = 0; ks < NK; ks++) {
        cp_waitn<0>();
        __syncthreads();
        if (ks + 1 < NK) issue(ks + 1);

        uint32_t As = sbase + (ks & 1) * STAGE32;
        uint32_t Bs = As + A_BYTES32;

        #pragma unroll
        for (int kk = 0; kk < 2; kk++) {
            uint32_t b[8];
            uint32_t bb = Bs + kk * 16 * (B_LD32 * 2) + wn * 64 + b_lane;
            ldsm4t(b[0], b[1], b[2], b[3], bb);
            ldsm4t(b[4], b[5], b[6], b[7], bb + 32);
            #pragma unroll
            for (int i = 0; i < 4; i++) {
                uint32_t a[4];
                ldsm4(a[0], a[1], a[2], a[3],
                      As + (uint32_t)((wm * 64 + i * 16) * (A_LD32 * 2)) + kk * 32 + a_lane);
                #pragma unroll
                for (int jn = 0; jn < 4; jn++)
                    mma16816(acc[i][jn], a, &b[jn * 2]);
            }
        }
    }
}

// ---------------- epilogues ----------------
__device__ __forceinline__ void epi1(int e, int ne, int m0, int n0, int wm, int wn,
                                     int lane, float (&acc)[4][4][4],
                                     const float* __restrict__ bin) {
    int gid = lane >> 2, t4 = lane & 3;
    #pragma unroll
    for (int i = 0; i < 4; i++) {
        int r0 = m0 + wm * 64 + i * 16 + gid;
        int r1 = r0 + 8;
        #pragma unroll
        for (int jn = 0; jn < 4; jn++) {
            int col = n0 + wn * 32 + jn * 8 + t4 * 2;
            float b0 = bin[e * HDIM + col], b1 = bin[e * HDIM + col + 1];
            if (r0 < ne) {
                float v0 = acc[i][jn][0] + b0;
                float v1 = acc[i][jn][1] + b1;
                v0 = 0.5f * v0 * (1.0f + erff(v0 * 0.70710678118654752f));
                v1 = 0.5f * v1 * (1.0f + erff(v1 * 0.70710678118654752f));
                *(__half2*)(g_h16 + ((size_t)e * CAPE + r0) * HDIM + col) =
                    __halves2half2(__float2half_rn(v0), __float2half_rn(v1));
            }
            if (r1 < ne) {
                float v2 = acc[i][jn][2] + b0;
                float v3 = acc[i][jn][3] + b1;
                v2 = 0.5f * v2 * (1.0f + erff(v2 * 0.70710678118654752f));
                v3 = 0.5f * v3 * (1.0f + erff(v3 * 0.70710678118654752f));
                *(__half2*)(g_h16 + ((size_t)e * CAPE + r1) * HDIM + col) =
                    __halves2half2(__float2half_rn(v2), __float2half_rn(v3));
            }
        }
    }
}

__device__ __forceinline__ void epi2(int e, int ne, int m0, int n0, int wm, int wn,
                                     int lane, float (&acc)[4][4][4],
                                     const float* __restrict__ bout,
                                     float* __restrict__ out) {
    int gid = lane >> 2, t4 = lane & 3;
    #pragma unroll
    for (int i = 0; i < 4; i++) {
        int r0 = m0 + wm * 64 + i * 16 + gid;
        int r1 = r0 + 8;
        int tok0 = -1, tok1 = -1; float wt0 = 0.0f, wt1 = 0.0f;
        if (r0 < ne) { tok0 = g_tokens[e * CAPE + r0]; wt0 = g_wts[e * CAPE + r0]; }
        if (r1 < ne) { tok1 = g_tokens[e * CAPE + r1]; wt1 = g_wts[e * CAPE + r1]; }
        #pragma unroll
        for (int jn = 0; jn < 4; jn++) {
            int col = n0 + wn * 32 + jn * 8 + t4 * 2;
            float b0 = bout[e * DDIM + col], b1 = bout[e * DDIM + col + 1];
            if (tok0 >= 0) {
                atomicAdd(out + (size_t)tok0 * DDIM + col,     wt0 * (acc[i][jn][0] + b0));
                atomicAdd(out + (size_t)tok0 * DDIM + col + 1, wt0 * (acc[i][jn][1] + b1));
            }
            if (tok1 >= 0) {
                atomicAdd(out + (size_t)tok1 * DDIM + col,     wt1 * (acc[i][jn][2] + b0));
                atomicAdd(out + (size_t)tok1 * DDIM + col + 1, wt1 * (acc[i][jn][3] + b1));
            }
        }
    }
}

// ---------------- gemm kernels ----------------
__global__ __launch_bounds__(256, 2) void k_gemm1_dyn(const float* __restrict__ bin) {
    extern __shared__ __align__(32) char dsm[];
    int e  = blockIdx.z;
    int ne = g_counts[e];
    int m0 = blockIdx.y * 128;
    if (m0 >= ne) return;
    int n0 = blockIdx.x * 128;
    int tid = threadIdx.x, wid = tid >> 5, lane = tid & 31;
    int wm = wid >> 2, wn = wid & 3;

    float acc[4][4][4];
    #pragma unroll
    for (int i = 0; i < 4; i++)
        #pragma unroll
        for (int j = 0; j < 4; j++)
            #pragma unroll
            for (int q = 0; q < 4; q++) acc[i][j][q] = 0.0f;

    mainloop64<DDIM, HDIM>(g_x16, g_w1 + (size_t)e * DDIM * HDIM + n0,
                           g_tokens + e * CAPE, m0, ne, dsm, acc, wm, wn);
    epi1(e, ne, m0, n0, wm, wn, lane, acc, bin);
}

__global__ __launch_bounds__(256, 2) void k_gemm2_dyn(const float* __restrict__ bout,
                                                      float* __restrict__ out) {
    extern __shared__ __align__(32) char dsm[];
    int e  = blockIdx.z;
    int ne = g_counts[e];
    int m0 = blockIdx.y * 128;
    if (m0 >= ne) return;
    int n0 = blockIdx.x * 128;
    int tid = threadIdx.x, wid = tid >> 5, lane = tid & 31;
    int wm = wid >> 2, wn = wid & 3;

    float acc[4][4][4];
    #pragma unroll
    for (int i = 0; i < 4; i++)
        #pragma unroll
        for (int j = 0; j < 4; j++)
            #pragma unroll
            for (int q = 0; q < 4; q++) acc[i][j][q] = 0.0f;

    mainloop64<HDIM, DDIM>(g_h16 + (size_t)e * CAPE * HDIM,
                           g_w2 + (size_t)e * HDIM * DDIM + n0,
                           nullptr, m0, ne, dsm, acc, wm, wn);
    epi2(e, ne, m0, n0, wm, wn, lane, acc, bout, out);
}

__global__ __launch_bounds__(256) void k_gemm1_sta(const float* __restrict__ bin) {
    __shared__ __align__(32) char dsm[SMEM_STA];
    int e  = blockIdx.z;
    int ne = g_counts[e];
    int m0 = blockIdx.y * 128;
    if (m0 >= ne) return;
    int n0 = blockIdx.x * 128;
    int tid = threadIdx.x, wid = tid >> 5, lane = tid & 31;
    int wm = wid >> 2, wn = wid & 3;

    float acc[4][4][4];
    #pragma unroll
    for (int i = 0; i < 4; i++)
        #pragma unroll
        for (int j = 0; j < 4; j++)
            #pragma unroll
            for (int q = 0; q < 4; q++) acc[i][j][q] = 0.0f;

    mainloop32<DDIM, HDIM>(g_x16, g_w1 + (size_t)e * DDIM * HDIM + n0,
                           g_tokens + e * CAPE, m0, ne, dsm, acc, wm, wn);
    epi1(e, ne, m0, n0, wm, wn, lane, acc, bin);
}

__global__ __launch_bounds__(256) void k_gemm2_sta(const float* __restrict__ bout,
                                                   float* __restrict__ out) {
    __shared__ __align__(32) char dsm[SMEM_STA];
    int e  = blockIdx.z;
    int ne = g_counts[e];
    int m0 = blockIdx.y * 128;
    if (m0 >= ne) return;
    int n0 = blockIdx.x * 128;
    int tid = threadIdx.x, wid = tid >> 5, lane = tid & 31;
    int wm = wid >> 2, wn = wid & 3;

    float acc[4][4][4];
    #pragma unroll
    for (int i = 0; i < 4; i++)
        #pragma unroll
        for (int j = 0; j < 4; j++)
            #pragma unroll
            for (int q = 0; q < 4; q++) acc[i][j][q] = 0.0f;

    mainloop32<HDIM, DDIM>(g_h16 + (size_t)e * CAPE * HDIM,
                           g_w2 + (size_t)e * HDIM * DDIM + n0,
                           nullptr, m0, ne, dsm, acc, wm, wn);
    epi2(e, ne, m0, n0, wm, wn, lane, acc, bout, out);
}

// ---------------- launch ----------------
extern "C" void kernel_launch(void* const* d_in, const int* in_sizes, int n_in,
                              void* d_out, int out_size) {
    const float* x    = (const float*)d_in[0];
    const float* rw   = (const float*)d_in[1];
    const float* Win  = (const float*)d_in[2];
    const float* bin  = (const float*)d_in[3];
    const float* Wout = (const float*)d_in[4];
    const float* bout = (const float*)d_in[5];
    float* out = (float*)d_out;

    cudaError_t a1 = cudaFuncSetAttribute(
        k_gemm1_dyn, cudaFuncAttributeMaxDynamicSharedMemorySize, SMEM_DYN);
    cudaError_t a2 = cudaFuncSetAttribute(
        k_gemm2_dyn, cudaFuncAttributeMaxDynamicSharedMemorySize, SMEM_DYN);
    bool use_dyn = (a1 == cudaSuccess) && (a2 == cudaSuccess);

    dim3 g1(HDIM / 128, CAPE / 128, NEXP);
    dim3 g2(DDIM / 128, CAPE / 128, NEXP);

    k_cvt_x<<<1024, 256>>>(x);                   // also zeroes routing state
    k_router<<<NTOK / 8, 256>>>(x, rw);
    k_cvt_w1<<<8192, 256>>>(Win);                // one 16-elem chunk per thread
    if (use_dyn) k_gemm1_dyn<<<g1, 256, SMEM_DYN>>>(bin);
    else         k_gemm1_sta<<<g1, 256>>>(bin);
    k_cvt_w2<<<8192, 256>>>(Wout);
    k_zero_out<<<512, 256>>>(out);
    if (use_dyn) k_gemm2_dyn<<<g2, 256, SMEM_DYN>>>(bout, out);
    else         k_gemm2_sta<<<g2, 256>>>(bout, out);
    k_aux<<<1, 32>>>(out, out_size);
}

// round 13
// speedup vs baseline: 1.0555x; 1.0116x over previous
#include <cuda_runtime.h>
#include <cuda_fp16.h>
#include <math.h>
#include <stdint.h>

// ---------------- problem constants ----------------
#define DDIM 1024
#define HDIM 4096
#define NEXP 8
#define NTOK 4096
#define CAPE 4096

// ---------------- tiling (dyn path: KSTAGE=64, 3 stages, 8 warps) ----------------
#define KS64 64
#define A_LD64 72                         // 64 halves + 8 skew
#define B_LD64 136                        // 128 halves + 8 skew
#define A_BYTES64 (128 * A_LD64 * 2)      // 18432
#define B_BYTES64 (KS64 * B_LD64 * 2)     // 17408
#define STAGE64 (A_BYTES64 + B_BYTES64)   // 35840
#define SMEM_DYN (3 * STAGE64)            // 107520

// ---------------- tiling (static fallback: KSTAGE=32, 2 stages, 8 warps) ----------------
#define KS32 32
#define A_LD32 40
#define B_LD32 136
#define A_BYTES32 (128 * A_LD32 * 2)      // 10240
#define B_BYTES32 (KS32 * B_LD32 * 2)     // 8704
#define STAGE32 (A_BYTES32 + B_BYTES32)   // 18944
#define SMEM_STA (2 * STAGE32)            // 37888

// ---------------- device scratch ----------------
__device__ int    g_counts[NEXP];
__device__ int    g_tokens[NEXP * CAPE];
__device__ float  g_wts[NEXP * CAPE];
__device__ float  g_probsum[NEXP];
__device__ __half g_x16[(size_t)NTOK * DDIM];
__device__ __half g_w1[(size_t)NEXP * DDIM * HDIM];
__device__ __half g_w2[(size_t)NEXP * HDIM * DDIM];
__device__ __half g_h16[(size_t)NEXP * CAPE * HDIM];

// ---------------- helpers ----------------
__device__ __forceinline__ uint32_t smem_u32(const void* p) {
    uint32_t a;
    asm("{ .reg .u64 t; cvta.to.shared.u64 t, %1; cvt.u32.u64 %0, t; }" : "=r"(a) : "l"(p));
    return a;
}
__device__ __forceinline__ void cp16(uint32_t s, const void* g) {
    asm volatile("cp.async.cg.shared.global [%0], [%1], 16;\n" :: "r"(s), "l"(g) : "memory");
}
__device__ __forceinline__ void cp_commit() {
    asm volatile("cp.async.commit_group;\n" ::: "memory");
}
template <int N>
__device__ __forceinline__ void cp_waitn() {
    asm volatile("cp.async.wait_group %0;\n" :: "n"(N) : "memory");
}
__device__ __forceinline__ void ldsm4(uint32_t& r0, uint32_t& r1, uint32_t& r2, uint32_t& r3, uint32_t a) {
    asm volatile("ldmatrix.sync.aligned.m8n8.x4.shared.b16 {%0,%1,%2,%3}, [%4];"
                 : "=r"(r0), "=r"(r1), "=r"(r2), "=r"(r3) : "r"(a));
}
__device__ __forceinline__ void ldsm4t(uint32_t& r0, uint32_t& r1, uint32_t& r2, uint32_t& r3, uint32_t a) {
    asm volatile("ldmatrix.sync.aligned.m8n8.x4.trans.shared.b16 {%0,%1,%2,%3}, [%4];"
                 : "=r"(r0), "=r"(r1), "=r"(r2), "=r"(r3) : "r"(a));
}
__device__ __forceinline__ void mma16816(float* c, const uint32_t* a, const uint32_t* b) {
    asm volatile(
        "mma.sync.aligned.m16n8k16.row.col.f32.f16.f16.f32 "
        "{%0,%1,%2,%3}, {%4,%5,%6,%7}, {%8,%9}, {%0,%1,%2,%3};"
        : "+f"(c[0]), "+f"(c[1]), "+f"(c[2]), "+f"(c[3])
        : "r"(a[0]), "r"(a[1]), "r"(a[2]), "r"(a[3]), "r"(b[0]), "r"(b[1]));
}

// ---------------- converts (16 elems/thread, evict-first fp32 reads) ----------------
__device__ __forceinline__ void cvt16(const float* __restrict__ s,
                                      __half* __restrict__ d, size_t n) {
    size_t stride = (size_t)gridDim.x * blockDim.x * 16;
    for (size_t i = ((size_t)blockIdx.x * blockDim.x + threadIdx.x) * 16; i < n; i += stride) {
        float4 v0 = __ldcs((const float4*)(s + i));
        float4 v1 = __ldcs((const float4*)(s + i + 4));
        float4 v2 = __ldcs((const float4*)(s + i + 8));
        float4 v3 = __ldcs((const float4*)(s + i + 12));
        uint4 s0, s1;
        __half2 h;
        h = __halves2half2(__float2half_rn(v0.x), __float2half_rn(v0.y)); s0.x = *(uint32_t*)&h;
        h = __halves2half2(__float2half_rn(v0.z), __float2half_rn(v0.w)); s0.y = *(uint32_t*)&h;
        h = __halves2half2(__float2half_rn(v1.x), __float2half_rn(v1.y)); s0.z = *(uint32_t*)&h;
        h = __halves2half2(__float2half_rn(v1.z), __float2half_rn(v1.w)); s0.w = *(uint32_t*)&h;
        h = __halves2half2(__float2half_rn(v2.x), __float2half_rn(v2.y)); s1.x = *(uint32_t*)&h;
        h = __halves2half2(__float2half_rn(v2.z), __float2half_rn(v2.w)); s1.y = *(uint32_t*)&h;
        h = __halves2half2(__float2half_rn(v3.x), __float2half_rn(v3.y)); s1.z = *(uint32_t*)&h;
        h = __halves2half2(__float2half_rn(v3.z), __float2half_rn(v3.w)); s1.w = *(uint32_t*)&h;
        *(uint4*)(d + i)     = s0;
        *(uint4*)(d + i + 8) = s1;
    }
}

// cvt_w1 runs FIRST: also zeroes routing state for the router that follows.
__global__ void k_cvt_w1(const float* __restrict__ s) {
    if (blockIdx.x == 0 && threadIdx.x < NEXP) {
        g_counts[threadIdx.x] = 0;
        g_probsum[threadIdx.x] = 0.0f;
    }
    cvt16(s, g_w1, (size_t)NEXP * DDIM * HDIM);
}

// cvt_w2 runs AFTER router: absorbs zero_out and aux.
__global__ void k_cvt_w2(const float* __restrict__ s, float* __restrict__ out,
                         int out_size) {
    if (blockIdx.x == 0 && threadIdx.x == 0 && out_size > NTOK * DDIM) {
        float aux = 0.0f;
        for (int e = 0; e < NEXP; e++) {
            float avg_p = g_probsum[e] / (float)NTOK;
            float usage = (float)g_counts[e] / (float)(NTOK * 2);
            aux += avg_p * usage;
        }
        out[NTOK * DDIM] = (float)NEXP * aux;
    }
    // zero the output accumulator [0, NTOK*DDIM)
    {
        size_t n = (size_t)NTOK * DDIM;
        size_t stride = (size_t)gridDim.x * blockDim.x * 4;
        for (size_t i = ((size_t)blockIdx.x * blockDim.x + threadIdx.x) * 4; i < n; i += stride)
            *(float4*)(out + i) = make_float4(0.f, 0.f, 0.f, 0.f);
    }
    cvt16(s, g_w2, (size_t)NEXP * HDIM * DDIM);
}

// router: logits/softmax/top2 AND writes g_x16 (fp16 convert of x) in the same pass.
__global__ void k_router(const float* __restrict__ x, const float* __restrict__ rw) {
    int gwarp = (blockIdx.x * blockDim.x + threadIdx.x) >> 5;
    int lane  = threadIdx.x & 31;
    __shared__ float s_ps[NEXP];
    if (threadIdx.x < NEXP) s_ps[threadIdx.x] = 0.0f;
    __syncthreads();

    if (gwarp < NTOK) {
        const float* xr = x + (size_t)gwarp * DDIM;
        __half* xo = g_x16 + (size_t)gwarp * DDIM;
        float acc[NEXP];
        #pragma unroll
        for (int e = 0; e < NEXP; e++) acc[e] = 0.0f;
        for (int k = lane; k < DDIM; k += 32) {
            float xv = xr[k];
            xo[k] = __float2half_rn(xv);          // fused x convert
            const float* r = rw + k * NEXP;
            #pragma unroll
            for (int e = 0; e < NEXP; e++) acc[e] += xv * r[e];
        }
        #pragma unroll
        for (int off = 16; off > 0; off >>= 1)
            #pragma unroll
            for (int e = 0; e < NEXP; e++)
                acc[e] += __shfl_down_sync(0xffffffffu, acc[e], off);

        if (lane == 0) {
            float m = acc[0];
            #pragma unroll
            for (int e = 1; e < NEXP; e++) m = fmaxf(m, acc[e]);
            float p[NEXP]; float Z = 0.0f;
            #pragma unroll
            for (int e = 0; e < NEXP; e++) { p[e] = expf(acc[e] - m); Z += p[e]; }
            float invZ = 1.0f / Z;
            #pragma unroll
            for (int e = 0; e < NEXP; e++) p[e] *= invZ;

            int i1 = 0;
            #pragma unroll
            for (int e = 1; e < NEXP; e++) if (p[e] > p[i1]) i1 = e;
            int i2 = (i1 == 0) ? 1 : 0;
            #pragma unroll
            for (int e = 0; e < NEXP; e++) if (e != i1 && p[e] > p[i2]) i2 = e;

            float s  = p[i1] + p[i2] + 1e-8f;
            int pos1 = atomicAdd(&g_counts[i1], 1);
            g_tokens[i1 * CAPE + pos1] = gwarp;
            g_wts[i1 * CAPE + pos1]    = p[i1] / s;
            int pos2 = atomicAdd(&g_counts[i2], 1);
            g_tokens[i2 * CAPE + pos2] = gwarp;
            g_wts[i2 * CAPE + pos2]    = p[i2] / s;

            #pragma unroll
            for (int e = 0; e < NEXP; e++) atomicAdd(&s_ps[e], p[e]);
        }
    }
    __syncthreads();
    if (threadIdx.x < NEXP) atomicAdd(&g_probsum[threadIdx.x], s_ps[threadIdx.x]);
}

// ---------------- mainloop64: 8 warps, 64x32 warp tile, KS=64, 3 stages ----------------
template <int KTOT, int NS>
__device__ __forceinline__ void mainloop64(
    const __half* __restrict__ Abase,
    const __half* __restrict__ Bn0,
    const int* __restrict__ gather,
    int m0, int ne, char* dsm,
    float (&acc)[4][4][4], int wm, int wn)
{
    constexpr int STAGES = 3;
    const int tid = threadIdx.x;
    const int lane = tid & 31;
    uint32_t sbase = smem_u32(dsm);

    size_t aoff[4]; uint32_t adst[4];
    #pragma unroll
    for (int t = 0; t < 4; t++) {
        int c = tid + t * 256;
        int row = c >> 3, sub = c & 7;
        int m = m0 + row;
        int ridx = gather ? ((m < ne) ? gather[m] : 0) : m;
        aoff[t] = (size_t)ridx * KTOT + sub * 8;
        adst[t] = (uint32_t)(row * (A_LD64 * 2) + sub * 16);
    }
    size_t boff[4]; uint32_t bdst[4];
    #pragma unroll
    for (int t = 0; t < 4; t++) {
        int c = tid + t * 256;
        int row = c >> 4, sub = c & 15;
        boff[t] = (size_t)row * NS + sub * 8;
        bdst[t] = (uint32_t)(A_BYTES64 + row * (B_LD64 * 2) + sub * 16);
    }

    auto issue = [&](int ks) {
        uint32_t sb = sbase + (ks % STAGES) * STAGE64;
        int k0 = ks * KS64;
        #pragma unroll
        for (int t = 0; t < 4; t++) cp16(sb + adst[t], Abase + aoff[t] + k0);
        const __half* bk = Bn0 + (size_t)k0 * NS;
        #pragma unroll
        for (int t = 0; t < 4; t++) cp16(sb + bdst[t], bk + boff[t]);
        cp_commit();
    };

    const uint32_t a_lane = (uint32_t)((lane & 15) * (A_LD64 * 2) + (lane >> 4) * 16);
    const uint32_t b_lane = (uint32_t)((lane & 15) * (B_LD64 * 2) + (lane >> 4) * 16);

    constexpr int NK = KTOT / KS64;
    issue(0); issue(1);

    for (int ks = 0; ks < NK; ks++) {
        if (ks == NK - 1) cp_waitn<0>();
        else              cp_waitn<1>();
        __syncthreads();
        if (ks + 2 < NK) issue(ks + 2);

        uint32_t As = sbase + (ks % STAGES) * STAGE64;
        uint32_t Bs = As + A_BYTES64;

        #pragma unroll
        for (int kk = 0; kk < 4; kk++) {
            uint32_t b[8];
            uint32_t bb = Bs + kk * 16 * (B_LD64 * 2) + wn * 64 + b_lane;
            ldsm4t(b[0], b[1], b[2], b[3], bb);
            ldsm4t(b[4], b[5], b[6], b[7], bb + 32);
            #pragma unroll
            for (int i = 0; i < 4; i++) {
                uint32_t a[4];
                ldsm4(a[0], a[1], a[2], a[3],
                      As + (uint32_t)((wm * 64 + i * 16) * (A_LD64 * 2)) + kk * 32 + a_lane);
                #pragma unroll
                for (int jn = 0; jn < 4; jn++)
                    mma16816(acc[i][jn], a, &b[jn * 2]);
            }
        }
    }
}

// ---------------- mainloop32 (static fallback, 2-stage) ----------------
template <int KTOT, int NS>
__device__ __forceinline__ void mainloop32(
    const __half* __restrict__ Abase,
    const __half* __restrict__ Bn0,
    const int* __restrict__ gather,
    int m0, int ne, char* dsm,
    float (&acc)[4][4][4], int wm, int wn)
{
    const int tid = threadIdx.x;
    const int lane = tid & 31;
    uint32_t sbase = smem_u32(dsm);

    size_t aoff[2]; uint32_t adst[2];
    #pragma unroll
    for (int t = 0; t < 2; t++) {
        int c = tid + t * 256;
        int row = c >> 2, sub = c & 3;
        int m = m0 + row;
        int ridx = gather ? ((m < ne) ? gather[m] : 0) : m;
        aoff[t] = (size_t)ridx * KTOT + sub * 8;
        adst[t] = (uint32_t)(row * (A_LD32 * 2) + sub * 16);
    }
    size_t boff[2]; uint32_t bdst[2];
    #pragma unroll
    for (int t = 0; t < 2; t++) {
        int c = tid + t * 256;
        int row = c >> 4, sub = c & 15;
        boff[t] = (size_t)row * NS + sub * 8;
        bdst[t] = (uint32_t)(A_BYTES32 + row * (B_LD32 * 2) + sub * 16);
    }

    auto issue = [&](int ks) {
        uint32_t sb = sbase + (ks & 1) * STAGE32;
        int k0 = ks * KS32;
        cp16(sb + adst[0], Abase + aoff[0] + k0);
        cp16(sb + adst[1], Abase + aoff[1] + k0);
        const __half* bk = Bn0 + (size_t)k0 * NS;
        cp16(sb + bdst[0], bk + boff[0]);
        cp16(sb + bdst[1], bk + boff[1]);
        cp_commit();
    };

    const uint32_t a_lane = (uint32_t)((lane & 15) * (A_LD32 * 2) + (lane >> 4) * 16);
    const uint32_t b_lane = (uint32_t)((lane & 15) * (B_LD32 * 2) + (lane >> 4) * 16);

    constexpr int NK = KTOT / KS32;
    issue(0);

    for (int ks = 0; ks < NK; ks++) {
        cp_waitn<0>();
        __syncthreads();
        if (ks + 1 < NK) issue(ks + 1);

        uint32_t As = sbase + (ks & 1) * STAGE32;
        uint32_t Bs = As + A_BYTES32;

        #pragma unroll
        for (int kk = 0; kk < 2; kk++) {
            uint32_t b[8];
            uint32_t bb = Bs + kk * 16 * (B_LD32 * 2) + wn * 64 + b_lane;
            ldsm4t(b[0], b[1], b[2], b[3], bb);
            ldsm4t(b[4], b[5], b[6], b[7], bb + 32);
            #pragma unroll
            for (int i = 0; i < 4; i++) {
                uint32_t a[4];
                ldsm4(a[0], a[1], a[2], a[3],
                      As + (uint32_t)((wm * 64 + i * 16) * (A_LD32 * 2)) + kk * 32 + a_lane);
                #pragma unroll
                for (int jn = 0; jn < 4; jn++)
                    mma16816(acc[i][jn], a, &b[jn * 2]);
            }
        }
    }
}

// ---------------- epilogues ----------------
__device__ __forceinline__ void epi1(int e, int ne, int m0, int n0, int wm, int wn,
                                     int lane, float (&acc)[4][4][4],
                                     const float* __restrict__ bin) {
    int gid = lane >> 2, t4 = lane & 3;
    #pragma unroll
    for (int i = 0; i < 4; i++) {
        int r0 = m0 + wm * 64 + i * 16 + gid;
        int r1 = r0 + 8;
        #pragma unroll
        for (int jn = 0; jn < 4; jn++) {
            int col = n0 + wn * 32 + jn * 8 + t4 * 2;
            float b0 = bin[e * HDIM + col], b1 = bin[e * HDIM + col + 1];
            if (r0 < ne) {
                float v0 = acc[i][jn][0] + b0;
                float v1 = acc[i][jn][1] + b1;
                v0 = 0.5f * v0 * (1.0f + erff(v0 * 0.70710678118654752f));
                v1 = 0.5f * v1 * (1.0f + erff(v1 * 0.70710678118654752f));
                *(__half2*)(g_h16 + ((size_t)e * CAPE + r0) * HDIM + col) =
                    __halves2half2(__float2half_rn(v0), __float2half_rn(v1));
            }
            if (r1 < ne) {
                float v2 = acc[i][jn][2] + b0;
                float v3 = acc[i][jn][3] + b1;
                v2 = 0.5f * v2 * (1.0f + erff(v2 * 0.70710678118654752f));
                v3 = 0.5f * v3 * (1.0f + erff(v3 * 0.70710678118654752f));
                *(__half2*)(g_h16 + ((size_t)e * CAPE + r1) * HDIM + col) =
                    __halves2half2(__float2half_rn(v2), __float2half_rn(v3));
            }
        }
    }
}

__device__ __forceinline__ void epi2(int e, int ne, int m0, int n0, int wm, int wn,
                                     int lane, float (&acc)[4][4][4],
                                     const float* __restrict__ bout,
                                     float* __restrict__ out) {
    int gid = lane >> 2, t4 = lane & 3;
    #pragma unroll
    for (int i = 0; i < 4; i++) {
        int r0 = m0 + wm * 64 + i * 16 + gid;
        int r1 = r0 + 8;
        int tok0 = -1, tok1 = -1; float wt0 = 0.0f, wt1 = 0.0f;
        if (r0 < ne) { tok0 = g_tokens[e * CAPE + r0]; wt0 = g_wts[e * CAPE + r0]; }
        if (r1 < ne) { tok1 = g_tokens[e * CAPE + r1]; wt1 = g_wts[e * CAPE + r1]; }
        #pragma unroll
        for (int jn = 0; jn < 4; jn++) {
            int col = n0 + wn * 32 + jn * 8 + t4 * 2;
            float b0 = bout[e * DDIM + col], b1 = bout[e * DDIM + col + 1];
            if (tok0 >= 0) {
                atomicAdd(out + (size_t)tok0 * DDIM + col,     wt0 * (acc[i][jn][0] + b0));
                atomicAdd(out + (size_t)tok0 * DDIM + col + 1, wt0 * (acc[i][jn][1] + b1));
            }
            if (tok1 >= 0) {
                atomicAdd(out + (size_t)tok1 * DDIM + col,     wt1 * (acc[i][jn][2] + b0));
                atomicAdd(out + (size_t)tok1 * DDIM + col + 1, wt1 * (acc[i][jn][3] + b1));
            }
        }
    }
}

// ---------------- gemm kernels ----------------
__global__ __launch_bounds__(256, 2) void k_gemm1_dyn(const float* __restrict__ bin) {
    extern __shared__ __align__(32) char dsm[];
    int e  = blockIdx.z;
    int ne = g_counts[e];
    int m0 = blockIdx.y * 128;
    if (m0 >= ne) return;
    int n0 = blockIdx.x * 128;
    int tid = threadIdx.x, wid = tid >> 5, lane = tid & 31;
    int wm = wid >> 2, wn = wid & 3;

    float acc[4][4][4];
    #pragma unroll
    for (int i = 0; i < 4; i++)
        #pragma unroll
        for (int j = 0; j < 4; j++)
            #pragma unroll
            for (int q = 0; q < 4; q++) acc[i][j][q] = 0.0f;

    mainloop64<DDIM, HDIM>(g_x16, g_w1 + (size_t)e * DDIM * HDIM + n0,
                           g_tokens + e * CAPE, m0, ne, dsm, acc, wm, wn);
    epi1(e, ne, m0, n0, wm, wn, lane, acc, bin);
}

__global__ __launch_bounds__(256, 2) void k_gemm2_dyn(const float* __restrict__ bout,
                                                      float* __restrict__ out) {
    extern __shared__ __align__(32) char dsm[];
    int e  = blockIdx.z;
    int ne = g_counts[e];
    int m0 = blockIdx.y * 128;
    if (m0 >= ne) return;
    int n0 = blockIdx.x * 128;
    int tid = threadIdx.x, wid = tid >> 5, lane = tid & 31;
    int wm = wid >> 2, wn = wid & 3;

    float acc[4][4][4];
    #pragma unroll
    for (int i = 0; i < 4; i++)
        #pragma unroll
        for (int j = 0; j < 4; j++)
            #pragma unroll
            for (int q = 0; q < 4; q++) acc[i][j][q] = 0.0f;

    mainloop64<HDIM, DDIM>(g_h16 + (size_t)e * CAPE * HDIM,
                           g_w2 + (size_t)e * HDIM * DDIM + n0,
                           nullptr, m0, ne, dsm, acc, wm, wn);
    epi2(e, ne, m0, n0, wm, wn, lane, acc, bout, out);
}

__global__ __launch_bounds__(256) void k_gemm1_sta(const float* __restrict__ bin) {
    __shared__ __align__(32) char dsm[SMEM_STA];
    int e  = blockIdx.z;
    int ne = g_counts[e];
    int m0 = blockIdx.y * 128;
    if (m0 >= ne) return;
    int n0 = blockIdx.x * 128;
    int tid = threadIdx.x, wid = tid >> 5, lane = tid & 31;
    int wm = wid >> 2, wn = wid & 3;

    float acc[4][4][4];
    #pragma unroll
    for (int i = 0; i < 4; i++)
        #pragma unroll
        for (int j = 0; j < 4; j++)
            #pragma unroll
            for (int q = 0; q < 4; q++) acc[i][j][q] = 0.0f;

    mainloop32<DDIM, HDIM>(g_x16, g_w1 + (size_t)e * DDIM * HDIM + n0,
                           g_tokens + e * CAPE, m0, ne, dsm, acc, wm, wn);
    epi1(e, ne, m0, n0, wm, wn, lane, acc, bin);
}

__global__ __launch_bounds__(256) void k_gemm2_sta(const float* __restrict__ bout,
                                                   float* __restrict__ out) {
    __shared__ __align__(32) char dsm[SMEM_STA];
    int e  = blockIdx.z;
    int ne = g_counts[e];
    int m0 = blockIdx.y * 128;
    if (m0 >= ne) return;
    int n0 = blockIdx.x * 128;
    int tid = threadIdx.x, wid = tid >> 5, lane = tid & 31;
    int wm = wid >> 2, wn = wid & 3;

    float acc[4][4][4];
    #pragma unroll
    for (int i = 0; i < 4; i++)
        #pragma unroll
        for (int j = 0; j < 4; j++)
            #pragma unroll
            for (int q = 0; q < 4; q++) acc[i][j][q] = 0.0f;

    mainloop32<HDIM, DDIM>(g_h16 + (size_t)e * CAPE * HDIM,
                           g_w2 + (size_t)e * HDIM * DDIM + n0,
                           nullptr, m0, ne, dsm, acc, wm, wn);
    epi2(e, ne, m0, n0, wm, wn, lane, acc, bout, out);
}

// ---------------- launch ----------------
extern "C" void kernel_launch(void* const* d_in, const int* in_sizes, int n_in,
                              void* d_out, int out_size) {
    const float* x    = (const float*)d_in[0];
    const float* rw   = (const float*)d_in[1];
    const float* Win  = (const float*)d_in[2];
    const float* bin  = (const float*)d_in[3];
    const float* Wout = (const float*)d_in[4];
    const float* bout = (const float*)d_in[5];
    float* out = (float*)d_out;

    cudaError_t a1 = cudaFuncSetAttribute(
        k_gemm1_dyn, cudaFuncAttributeMaxDynamicSharedMemorySize, SMEM_DYN);
    cudaError_t a2 = cudaFuncSetAttribute(
        k_gemm2_dyn, cudaFuncAttributeMaxDynamicSharedMemorySize, SMEM_DYN);
    bool use_dyn = (a1 == cudaSuccess) && (a2 == cudaSuccess);

    dim3 g1(HDIM / 128, CAPE / 128, NEXP);
    dim3 g2(DDIM / 128, CAPE / 128, NEXP);

    k_cvt_w1<<<8192, 256>>>(Win);                    // zeroes routing state too
    k_router<<<NTOK / 8, 256>>>(x, rw);              // also converts x -> g_x16
    if (use_dyn) k_gemm1_dyn<<<g1, 256, SMEM_DYN>>>(bin);
    else         k_gemm1_sta<<<g1, 256>>>(bin);
    k_cvt_w2<<<8192, 256>>>(Wout, out, out_size);    // + zero_out + aux
    if (use_dyn) k_gemm2_dyn<<<g2, 256, SMEM_DYN>>>(bout, out);
    else         k_gemm2_sta<<<g2, 256>>>(bout, out);
}

// round 14
// speedup vs baseline: 1.0822x; 1.0253x over previous
#include <cuda_runtime.h>
#include <cuda_fp16.h>
#include <math.h>
#include <stdint.h>

// ---------------- problem constants ----------------
#define DDIM 1024
#define HDIM 4096
#define NEXP 8
#define NTOK 4096
#define CAPE 4096

// ---------------- tiling (dyn path: KSTAGE=64, 3 stages, 8 warps) ----------------
#define KS64 64
#define A_LD64 72
#define B_LD64 136
#define A_BYTES64 (128 * A_LD64 * 2)      // 18432
#define B_BYTES64 (KS64 * B_LD64 * 2)     // 17408
#define STAGE64 (A_BYTES64 + B_BYTES64)   // 35840
#define SMEM_DYN (3 * STAGE64)            // 107520

// ---------------- tiling (static fallback: KSTAGE=32, 2 stages) ----------------
#define KS32 32
#define A_LD32 40
#define B_LD32 136
#define A_BYTES32 (128 * A_LD32 * 2)
#define B_BYTES32 (KS32 * B_LD32 * 2)
#define STAGE32 (A_BYTES32 + B_BYTES32)
#define SMEM_STA (2 * STAGE32)

// ---------------- device scratch ----------------
__device__ int    g_counts[NEXP];
__device__ int    g_tokens[NEXP * CAPE];
__device__ float  g_wts[NEXP * CAPE];
__device__ float  g_probsum[NEXP];
__device__ __half g_x16[(size_t)NTOK * DDIM];
__device__ __half g_w1[(size_t)NEXP * DDIM * HDIM];
__device__ __half g_w2[(size_t)NEXP * HDIM * DDIM];
__device__ __half g_h16[(size_t)NEXP * CAPE * HDIM];

// ---------------- helpers ----------------
__device__ __forceinline__ uint32_t smem_u32(const void* p) {
    uint32_t a;
    asm("{ .reg .u64 t; cvta.to.shared.u64 t, %1; cvt.u32.u64 %0, t; }" : "=r"(a) : "l"(p));
    return a;
}
__device__ __forceinline__ void cp16(uint32_t s, const void* g) {
    asm volatile("cp.async.cg.shared.global [%0], [%1], 16;\n" :: "r"(s), "l"(g) : "memory");
}
__device__ __forceinline__ void cp_commit() {
    asm volatile("cp.async.commit_group;\n" ::: "memory");
}
template <int N>
__device__ __forceinline__ void cp_waitn() {
    asm volatile("cp.async.wait_group %0;\n" :: "n"(N) : "memory");
}
__device__ __forceinline__ void ldsm4(uint32_t& r0, uint32_t& r1, uint32_t& r2, uint32_t& r3, uint32_t a) {
    asm volatile("ldmatrix.sync.aligned.m8n8.x4.shared.b16 {%0,%1,%2,%3}, [%4];"
                 : "=r"(r0), "=r"(r1), "=r"(r2), "=r"(r3) : "r"(a));
}
__device__ __forceinline__ void ldsm4t(uint32_t& r0, uint32_t& r1, uint32_t& r2, uint32_t& r3, uint32_t a) {
    asm volatile("ldmatrix.sync.aligned.m8n8.x4.trans.shared.b16 {%0,%1,%2,%3}, [%4];"
                 : "=r"(r0), "=r"(r1), "=r"(r2), "=r"(r3) : "r"(a));
}
__device__ __forceinline__ void mma16816(float* c, const uint32_t* a, const uint32_t* b) {
    asm volatile(
        "mma.sync.aligned.m16n8k16.row.col.f32.f16.f16.f32 "
        "{%0,%1,%2,%3}, {%4,%5,%6,%7}, {%8,%9}, {%0,%1,%2,%3};"
        : "+f"(c[0]), "+f"(c[1]), "+f"(c[2]), "+f"(c[3])
        : "r"(a[0]), "r"(a[1]), "r"(a[2]), "r"(a[3]), "r"(b[0]), "r"(b[1]));
}

// one 16-elem fp32->fp16 chunk, evict-first reads
__device__ __forceinline__ void cvt_chunk16(const float* __restrict__ s,
                                            __half* __restrict__ d, size_t i) {
    float4 v0 = __ldcs((const float4*)(s + i));
    float4 v1 = __ldcs((const float4*)(s + i + 4));
    float4 v2 = __ldcs((const float4*)(s + i + 8));
    float4 v3 = __ldcs((const float4*)(s + i + 12));
    uint4 s0, s1;
    __half2 h;
    h = __halves2half2(__float2half_rn(v0.x), __float2half_rn(v0.y)); s0.x = *(uint32_t*)&h;
    h = __halves2half2(__float2half_rn(v0.z), __float2half_rn(v0.w)); s0.y = *(uint32_t*)&h;
    h = __halves2half2(__float2half_rn(v1.x), __float2half_rn(v1.y)); s0.z = *(uint32_t*)&h;
    h = __halves2half2(__float2half_rn(v1.z), __float2half_rn(v1.w)); s0.w = *(uint32_t*)&h;
    h = __halves2half2(__float2half_rn(v2.x), __float2half_rn(v2.y)); s1.x = *(uint32_t*)&h;
    h = __halves2half2(__float2half_rn(v2.z), __float2half_rn(v2.w)); s1.y = *(uint32_t*)&h;
    h = __halves2half2(__float2half_rn(v3.x), __float2half_rn(v3.y)); s1.z = *(uint32_t*)&h;
    h = __halves2half2(__float2half_rn(v3.z), __float2half_rn(v3.w)); s1.w = *(uint32_t*)&h;
    *(uint4*)(d + i)     = s0;
    *(uint4*)(d + i + 8) = s1;
}

// ---------------- init: zero routing state ----------------
__global__ void k_init() {
    if (threadIdx.x < NEXP) {
        g_counts[threadIdx.x] = 0;
        g_probsum[threadIdx.x] = 0.0f;
    }
}

// ---------------- fused router + W_in convert ----------------
// blocks [0,512): router (8 warps/block, 1 warp per token, also writes g_x16)
// blocks [512, 512+8192): convert W_in (one 16-elem chunk per thread)
#define RBLK 512
__global__ void k_route_cvtw1(const float* __restrict__ x,
                              const float* __restrict__ rw,
                              const float* __restrict__ w1src) {
    if (blockIdx.x >= RBLK) {
        size_t i = (((size_t)(blockIdx.x - RBLK)) * 256 + threadIdx.x) * 16;
        cvt_chunk16(w1src, g_w1, i);   // |W1| = 8192*256*16 exactly
        return;
    }

    int gwarp = (blockIdx.x * blockDim.x + threadIdx.x) >> 5;
    int lane  = threadIdx.x & 31;
    __shared__ float s_ps[NEXP];
    if (threadIdx.x < NEXP) s_ps[threadIdx.x] = 0.0f;
    __syncthreads();

    {
        const float* xr = x + (size_t)gwarp * DDIM;
        __half* xo = g_x16 + (size_t)gwarp * DDIM;
        float acc[NEXP];
        #pragma unroll
        for (int e = 0; e < NEXP; e++) acc[e] = 0.0f;
        for (int k = lane; k < DDIM; k += 32) {
            float xv = xr[k];
            xo[k] = __float2half_rn(xv);          // fused x convert
            const float* r = rw + k * NEXP;
            #pragma unroll
            for (int e = 0; e < NEXP; e++) acc[e] += xv * r[e];
        }
        #pragma unroll
        for (int off = 16; off > 0; off >>= 1)
            #pragma unroll
            for (int e = 0; e < NEXP; e++)
                acc[e] += __shfl_down_sync(0xffffffffu, acc[e], off);

        if (lane == 0) {
            float m = acc[0];
            #pragma unroll
            for (int e = 1; e < NEXP; e++) m = fmaxf(m, acc[e]);
            float p[NEXP]; float Z = 0.0f;
            #pragma unroll
            for (int e = 0; e < NEXP; e++) { p[e] = expf(acc[e] - m); Z += p[e]; }
            float invZ = 1.0f / Z;
            #pragma unroll
            for (int e = 0; e < NEXP; e++) p[e] *= invZ;

            int i1 = 0;
            #pragma unroll
            for (int e = 1; e < NEXP; e++) if (p[e] > p[i1]) i1 = e;
            int i2 = (i1 == 0) ? 1 : 0;
            #pragma unroll
            for (int e = 0; e < NEXP; e++) if (e != i1 && p[e] > p[i2]) i2 = e;

            float s  = p[i1] + p[i2] + 1e-8f;
            int pos1 = atomicAdd(&g_counts[i1], 1);
            g_tokens[i1 * CAPE + pos1] = gwarp;
            g_wts[i1 * CAPE + pos1]    = p[i1] / s;
            int pos2 = atomicAdd(&g_counts[i2], 1);
            g_tokens[i2 * CAPE + pos2] = gwarp;
            g_wts[i2 * CAPE + pos2]    = p[i2] / s;

            #pragma unroll
            for (int e = 0; e < NEXP; e++) atomicAdd(&s_ps[e], p[e]);
        }
    }
    __syncthreads();
    if (threadIdx.x < NEXP) atomicAdd(&g_probsum[threadIdx.x], s_ps[threadIdx.x]);
}

// ---------------- gemm1 prologue: convert W_out slice + zero out slice + aux ----------------
__device__ __forceinline__ void gemm1_prologue(const float* __restrict__ w2src,
                                               float* __restrict__ out, int out_size) {
    int bid = blockIdx.z * (gridDim.x * gridDim.y) + blockIdx.y * gridDim.x + blockIdx.x;
    int tid = threadIdx.x;
    // aux loss (router done: stream order)
    if (bid == 0 && tid == 0 && out_size > NTOK * DDIM) {
        float aux = 0.0f;
        for (int e = 0; e < NEXP; e++) {
            float avg_p = g_probsum[e] / (float)NTOK;
            float usage = (float)g_counts[e] / (float)(NTOK * 2);
            aux += avg_p * usage;
        }
        out[NTOK * DDIM] = (float)NEXP * aux;
    }
    // convert one 16-elem chunk of W_out (|W2| = 8192*256*16 exactly)
    size_t ci = (((size_t)bid) * 256 + tid) * 16;
    cvt_chunk16(w2src, g_w2, ci);
    // zero 512-float slice of out (4M floats / 8192 CTAs)
    size_t z = ((size_t)bid) * 512 + tid * 2;
    *(float2*)(out + z) = make_float2(0.f, 0.f);
}

// ---------------- mainloop64 ----------------
template <int KTOT, int NS>
__device__ __forceinline__ void mainloop64(
    const __half* __restrict__ Abase,
    const __half* __restrict__ Bn0,
    const int* __restrict__ gather,
    int m0, int ne, char* dsm,
    float (&acc)[4][4][4], int wm, int wn)
{
    constexpr int STAGES = 3;
    const int tid = threadIdx.x;
    const int lane = tid & 31;
    uint32_t sbase = smem_u32(dsm);

    size_t aoff[4]; uint32_t adst[4];
    #pragma unroll
    for (int t = 0; t < 4; t++) {
        int c = tid + t * 256;
        int row = c >> 3, sub = c & 7;
        int m = m0 + row;
        int ridx = gather ? ((m < ne) ? gather[m] : 0) : m;
        aoff[t] = (size_t)ridx * KTOT + sub * 8;
        adst[t] = (uint32_t)(row * (A_LD64 * 2) + sub * 16);
    }
    size_t boff[4]; uint32_t bdst[4];
    #pragma unroll
    for (int t = 0; t < 4; t++) {
        int c = tid + t * 256;
        int row = c >> 4, sub = c & 15;
        boff[t] = (size_t)row * NS + sub * 8;
        bdst[t] = (uint32_t)(A_BYTES64 + row * (B_LD64 * 2) + sub * 16);
    }

    auto issue = [&](int ks) {
        uint32_t sb = sbase + (ks % STAGES) * STAGE64;
        int k0 = ks * KS64;
        #pragma unroll
        for (int t = 0; t < 4; t++) cp16(sb + adst[t], Abase + aoff[t] + k0);
        const __half* bk = Bn0 + (size_t)k0 * NS;
        #pragma unroll
        for (int t = 0; t < 4; t++) cp16(sb + bdst[t], bk + boff[t]);
        cp_commit();
    };

    const uint32_t a_lane = (uint32_t)((lane & 15) * (A_LD64 * 2) + (lane >> 4) * 16);
    const uint32_t b_lane = (uint32_t)((lane & 15) * (B_LD64 * 2) + (lane >> 4) * 16);

    constexpr int NK = KTOT / KS64;
    issue(0); issue(1);

    for (int ks = 0; ks < NK; ks++) {
        if (ks == NK - 1) cp_waitn<0>();
        else              cp_waitn<1>();
        __syncthreads();
        if (ks + 2 < NK) issue(ks + 2);

        uint32_t As = sbase + (ks % STAGES) * STAGE64;
        uint32_t Bs = As + A_BYTES64;

        #pragma unroll
        for (int kk = 0; kk < 4; kk++) {
            uint32_t b[8];
            uint32_t bb = Bs + kk * 16 * (B_LD64 * 2) + wn * 64 + b_lane;
            ldsm4t(b[0], b[1], b[2], b[3], bb);
            ldsm4t(b[4], b[5], b[6], b[7], bb + 32);
            #pragma unroll
            for (int i = 0; i < 4; i++) {
                uint32_t a[4];
                ldsm4(a[0], a[1], a[2], a[3],
                      As + (uint32_t)((wm * 64 + i * 16) * (A_LD64 * 2)) + kk * 32 + a_lane);
                #pragma unroll
                for (int jn = 0; jn < 4; jn++)
                    mma16816(acc[i][jn], a, &b[jn * 2]);
            }
        }
    }
}

// ---------------- mainloop32 (static fallback) ----------------
template <int KTOT, int NS>
__device__ __forceinline__ void mainloop32(
    const __half* __restrict__ Abase,
    const __half* __restrict__ Bn0,
    const int* __restrict__ gather,
    int m0, int ne, char* dsm,
    float (&acc)[4][4][4], int wm, int wn)
{
    const int tid = threadIdx.x;
    const int lane = tid & 31;
    uint32_t sbase = smem_u32(dsm);

    size_t aoff[2]; uint32_t adst[2];
    #pragma unroll
    for (int t = 0; t < 2; t++) {
        int c = tid + t * 256;
        int row = c >> 2, sub = c & 3;
        int m = m0 + row;
        int ridx = gather ? ((m < ne) ? gather[m] : 0) : m;
        aoff[t] = (size_t)ridx * KTOT + sub * 8;
        adst[t] = (uint32_t)(row * (A_LD32 * 2) + sub * 16);
    }
    size_t boff[2]; uint32_t bdst[2];
    #pragma unroll
    for (int t = 0; t < 2; t++) {
        int c = tid + t * 256;
        int row = c >> 4, sub = c & 15;
        boff[t] = (size_t)row * NS + sub * 8;
        bdst[t] = (uint32_t)(A_BYTES32 + row * (B_LD32 * 2) + sub * 16);
    }

    auto issue = [&](int ks) {
        uint32_t sb = sbase + (ks & 1) * STAGE32;
        int k0 = ks * KS32;
        cp16(sb + adst[0], Abase + aoff[0] + k0);
        cp16(sb + adst[1], Abase + aoff[1] + k0);
        const __half* bk = Bn0 + (size_t)k0 * NS;
        cp16(sb + bdst[0], bk + boff[0]);
        cp16(sb + bdst[1], bk + boff[1]);
        cp_commit();
    };

    const uint32_t a_lane = (uint32_t)((lane & 15) * (A_LD32 * 2) + (lane >> 4) * 16);
    const uint32_t b_lane = (uint32_t)((lane & 15) * (B_LD32 * 2) + (lane >> 4) * 16);

    constexpr int NK = KTOT / KS32;
    issue(0);

    for (int ks = 0; ks < NK; ks++) {
        cp_waitn<0>();
        __syncthreads();
        if (ks + 1 < NK) issue(ks + 1);

        uint32_t As = sbase + (ks & 1) * STAGE32;
        uint32_t Bs = As + A_BYTES32;

        #pragma unroll
        for (int kk = 0; kk < 2; kk++) {
            uint32_t b[8];
            uint32_t bb = Bs + kk * 16 * (B_LD32 * 2) + wn * 64 + b_lane;
            ldsm4t(b[0], b[1], b[2], b[3], bb);
            ldsm4t(b[4], b[5], b[6], b[7], bb + 32);
            #pragma unroll
            for (int i = 0; i < 4; i++) {
                uint32_t a[4];
                ldsm4(a[0], a[1], a[2], a[3],
                      As + (uint32_t)((wm * 64 + i * 16) * (A_LD32 * 2)) + kk * 32 + a_lane);
                #pragma unroll
                for (int jn = 0; jn < 4; jn++)
                    mma16816(acc[i][jn], a, &b[jn * 2]);
            }
        }
    }
}

// ---------------- epilogues ----------------
__device__ __forceinline__ void epi1(int e, int ne, int m0, int n0, int wm, int wn,
                                     int lane, float (&acc)[4][4][4],
                                     const float* __restrict__ bin) {
    int gid = lane >> 2, t4 = lane & 3;
    #pragma unroll
    for (int i = 0; i < 4; i++) {
        int r0 = m0 + wm * 64 + i * 16 + gid;
        int r1 = r0 + 8;
        #pragma unroll
        for (int jn = 0; jn < 4; jn++) {
            int col = n0 + wn * 32 + jn * 8 + t4 * 2;
            float b0 = bin[e * HDIM + col], b1 = bin[e * HDIM + col + 1];
            if (r0 < ne) {
                float v0 = acc[i][jn][0] + b0;
                float v1 = acc[i][jn][1] + b1;
                v0 = 0.5f * v0 * (1.0f + erff(v0 * 0.70710678118654752f));
                v1 = 0.5f * v1 * (1.0f + erff(v1 * 0.70710678118654752f));
                *(__half2*)(g_h16 + ((size_t)e * CAPE + r0) * HDIM + col) =
                    __halves2half2(__float2half_rn(v0), __float2half_rn(v1));
            }
            if (r1 < ne) {
                float v2 = acc[i][jn][2] + b0;
                float v3 = acc[i][jn][3] + b1;
                v2 = 0.5f * v2 * (1.0f + erff(v2 * 0.70710678118654752f));
                v3 = 0.5f * v3 * (1.0f + erff(v3 * 0.70710678118654752f));
                *(__half2*)(g_h16 + ((size_t)e * CAPE + r1) * HDIM + col) =
                    __halves2half2(__float2half_rn(v2), __float2half_rn(v3));
            }
        }
    }
}

__device__ __forceinline__ void epi2(int e, int ne, int m0, int n0, int wm, int wn,
                                     int lane, float (&acc)[4][4][4],
                                     const float* __restrict__ bout,
                                     float* __restrict__ out) {
    int gid = lane >> 2, t4 = lane & 3;
    #pragma unroll
    for (int i = 0; i < 4; i++) {
        int r0 = m0 + wm * 64 + i * 16 + gid;
        int r1 = r0 + 8;
        int tok0 = -1, tok1 = -1; float wt0 = 0.0f, wt1 = 0.0f;
        if (r0 < ne) { tok0 = g_tokens[e * CAPE + r0]; wt0 = g_wts[e * CAPE + r0]; }
        if (r1 < ne) { tok1 = g_tokens[e * CAPE + r1]; wt1 = g_wts[e * CAPE + r1]; }
        #pragma unroll
        for (int jn = 0; jn < 4; jn++) {
            int col = n0 + wn * 32 + jn * 8 + t4 * 2;
            float b0 = bout[e * DDIM + col], b1 = bout[e * DDIM + col + 1];
            if (tok0 >= 0) {
                atomicAdd(out + (size_t)tok0 * DDIM + col,     wt0 * (acc[i][jn][0] + b0));
                atomicAdd(out + (size_t)tok0 * DDIM + col + 1, wt0 * (acc[i][jn][1] + b1));
            }
            if (tok1 >= 0) {
                atomicAdd(out + (size_t)tok1 * DDIM + col,     wt1 * (acc[i][jn][2] + b0));
                atomicAdd(out + (size_t)tok1 * DDIM + col + 1, wt1 * (acc[i][jn][3] + b1));
            }
        }
    }
}

// ---------------- gemm kernels ----------------
__global__ __launch_bounds__(256, 2) void k_gemm1_dyn(const float* __restrict__ bin,
                                                      const float* __restrict__ w2src,
                                                      float* __restrict__ out,
                                                      int out_size) {
    extern __shared__ __align__(32) char dsm[];
    gemm1_prologue(w2src, out, out_size);   // before early-exit!

    int e  = blockIdx.z;
    int ne = g_counts[e];
    int m0 = blockIdx.y * 128;
    if (m0 >= ne) return;
    int n0 = blockIdx.x * 128;
    int tid = threadIdx.x, wid = tid >> 5, lane = tid & 31;
    int wm = wid >> 2, wn = wid & 3;

    float acc[4][4][4];
    #pragma unroll
    for (int i = 0; i < 4; i++)
        #pragma unroll
        for (int j = 0; j < 4; j++)
            #pragma unroll
            for (int q = 0; q < 4; q++) acc[i][j][q] = 0.0f;

    mainloop64<DDIM, HDIM>(g_x16, g_w1 + (size_t)e * DDIM * HDIM + n0,
                           g_tokens + e * CAPE, m0, ne, dsm, acc, wm, wn);
    epi1(e, ne, m0, n0, wm, wn, lane, acc, bin);
}

__global__ __launch_bounds__(256, 2) void k_gemm2_dyn(const float* __restrict__ bout,
                                                      float* __restrict__ out) {
    extern __shared__ __align__(32) char dsm[];
    int e  = blockIdx.z;
    int ne = g_counts[e];
    int m0 = blockIdx.y * 128;
    if (m0 >= ne) return;
    int n0 = blockIdx.x * 128;
    int tid = threadIdx.x, wid = tid >> 5, lane = tid & 31;
    int wm = wid >> 2, wn = wid & 3;

    float acc[4][4][4];
    #pragma unroll
    for (int i = 0; i < 4; i++)
        #pragma unroll
        for (int j = 0; j < 4; j++)
            #pragma unroll
            for (int q = 0; q < 4; q++) acc[i][j][q] = 0.0f;

    mainloop64<HDIM, DDIM>(g_h16 + (size_t)e * CAPE * HDIM,
                           g_w2 + (size_t)e * HDIM * DDIM + n0,
                           nullptr, m0, ne, dsm, acc, wm, wn);
    epi2(e, ne, m0, n0, wm, wn, lane, acc, bout, out);
}

__global__ __launch_bounds__(256) void k_gemm1_sta(const float* __restrict__ bin,
                                                   const float* __restrict__ w2src,
                                                   float* __restrict__ out,
                                                   int out_size) {
    __shared__ __align__(32) char dsm[SMEM_STA];
    gemm1_prologue(w2src, out, out_size);

    int e  = blockIdx.z;
    int ne = g_counts[e];
    int m0 = blockIdx.y * 128;
    if (m0 >= ne) return;
    int n0 = blockIdx.x * 128;
    int tid = threadIdx.x, wid = tid >> 5, lane = tid & 31;
    int wm = wid >> 2, wn = wid & 3;

    float acc[4][4][4];
    #pragma unroll
    for (int i = 0; i < 4; i++)
        #pragma unroll
        for (int j = 0; j < 4; j++)
            #pragma unroll
            for (int q = 0; q < 4; q++) acc[i][j][q] = 0.0f;

    mainloop32<DDIM, HDIM>(g_x16, g_w1 + (size_t)e * DDIM * HDIM + n0,
                           g_tokens + e * CAPE, m0, ne, dsm, acc, wm, wn);
    epi1(e, ne, m0, n0, wm, wn, lane, acc, bin);
}

__global__ __launch_bounds__(256) void k_gemm2_sta(const float* __restrict__ bout,
                                                   float* __restrict__ out) {
    __shared__ __align__(32) char dsm[SMEM_STA];
    int e  = blockIdx.z;
    int ne = g_counts[e];
    int m0 = blockIdx.y * 128;
    if (m0 >= ne) return;
    int n0 = blockIdx.x * 128;
    int tid = threadIdx.x, wid = tid >> 5, lane = tid & 31;
    int wm = wid >> 2, wn = wid & 3;

    float acc[4][4][4];
    #pragma unroll
    for (int i = 0; i < 4; i++)
        #pragma unroll
        for (int j = 0; j < 4; j++)
            #pragma unroll
            for (int q = 0; q < 4; q++) acc[i][j][q] = 0.0f;

    mainloop32<HDIM, DDIM>(g_h16 + (size_t)e * CAPE * HDIM,
                           g_w2 + (size_t)e * HDIM * DDIM + n0,
                           nullptr, m0, ne, dsm, acc, wm, wn);
    epi2(e, ne, m0, n0, wm, wn, lane, acc, bout, out);
}

// ---------------- launch ----------------
extern "C" void kernel_launch(void* const* d_in, const int* in_sizes, int n_in,
                              void* d_out, int out_size) {
    const float* x    = (const float*)d_in[0];
    const float* rw   = (const float*)d_in[1];
    const float* Win  = (const float*)d_in[2];
    const float* bin  = (const float*)d_in[3];
    const float* Wout = (const float*)d_in[4];
    const float* bout = (const float*)d_in[5];
    float* out = (float*)d_out;

    cudaError_t a1 = cudaFuncSetAttribute(
        k_gemm1_dyn, cudaFuncAttributeMaxDynamicSharedMemorySize, SMEM_DYN);
    cudaError_t a2 = cudaFuncSetAttribute(
        k_gemm2_dyn, cudaFuncAttributeMaxDynamicSharedMemorySize, SMEM_DYN);
    bool use_dyn = (a1 == cudaSuccess) && (a2 == cudaSuccess);

    dim3 g1(HDIM / 128, CAPE / 128, NEXP);
    dim3 g2(DDIM / 128, CAPE / 128, NEXP);

    k_init<<<1, 32>>>();
    k_route_cvtw1<<<RBLK + 8192, 256>>>(x, rw, Win);      // router + W_in convert fused
    if (use_dyn) k_gemm1_dyn<<<g1, 256, SMEM_DYN>>>(bin, Wout, out, out_size);
    else         k_gemm1_sta<<<g1, 256>>>(bin, Wout, out, out_size);
    if (use_dyn) k_gemm2_dyn<<<g2, 256, SMEM_DYN>>>(bout, out);
    else         k_gemm2_sta<<<g2, 256>>>(bout, out);
}